// round 2
// baseline (speedup 1.0000x reference)
#include <cuda_runtime.h>
#include <cuda_bf16.h>

#define TT    1024
#define CC    256
#define E3    768
#define WINN  128
#define PADN  63
#define TPP   1150
#define LW    1023
#define SHIFTN 64
#define WPB   8
#define RB    136
#define RS    68
#define GSS   137

#define SM_G   (RB*GSS)                 // 18632
#define SM_ALL (2*SM_G + RB*RS + 2*RB + WINN + 2*64 + 1)
#define SMEM_BYTES (SM_ALL*4)

__device__ float g_z[TT*E3];
__device__ float g_acc[2*TPP*CC];
__device__ float g_wti[CC*E3];
__device__ float g_wto[CC*CC];
__device__ float g_wtp[CC*CC];
__device__ float g_y[TT*CC];
__device__ float g_colsum[CC];
__device__ float g_segate[CC];

__device__ __forceinline__ float cntf(int t) {
    int tp = t + PADN;
    int lmin = tp - 127; if (lmin < 0) lmin = 0;
    int lmax = tp;       if (lmax > 1022) lmax = 1022;
    return (float)(lmax - lmin + 1);
}

// ---------------- zero accumulators ----------------
__global__ void k_zero() {
    int i = blockIdx.x * 256 + threadIdx.x;
    if (i < 2*TPP*CC) g_acc[i] = 0.f;
    if (i < CC) g_colsum[i] = 0.f;
}

// ---------------- transpose weights ----------------
__global__ void k_transpose(const float* __restrict__ wi,
                            const float* __restrict__ wo,
                            const float* __restrict__ wp) {
    int idx = blockIdx.x * 256 + threadIdx.x;
    if (idx < E3*CC) {
        int e = idx >> 8, c = idx & 255;
        g_wti[c*E3 + e] = wi[idx];
    }
    if (idx < CC*CC) {
        int e = idx >> 8, c = idx & 255;
        g_wto[c*CC + e] = wo[idx];
        g_wtp[c*CC + e] = wp[idx];
    }
}

// ---------------- LayerNorm + z = LN(x) @ Win^T (bias hoisted out) --------
__global__ __launch_bounds__(256) void k_ln_z(const float* __restrict__ x,
                                              const float* __restrict__ lg,
                                              const float* __restrict__ lb) {
    __shared__ float Y[8][CC];
    __shared__ float sA[8][8], sB[8][8];
    int tid = threadIdx.x, warp = tid >> 5, lane = tid & 31;
    int row0 = blockIdx.x * 8;

    float gv = lg[tid], bv = lb[tid];
    float xv[8];
#pragma unroll
    for (int r = 0; r < 8; r++) {
        float v = x[(row0 + r)*CC + tid];
        xv[r] = v;
        float s = v, s2 = v*v;
#pragma unroll
        for (int o = 16; o; o >>= 1) {
            s  += __shfl_xor_sync(0xffffffffu, s, o);
            s2 += __shfl_xor_sync(0xffffffffu, s2, o);
        }
        if (lane == 0) { sA[r][warp] = s; sB[r][warp] = s2; }
    }
    __syncthreads();
#pragma unroll
    for (int r = 0; r < 8; r++) {
        float s = 0.f, s2 = 0.f;
#pragma unroll
        for (int w2 = 0; w2 < 8; w2++) { s += sA[r][w2]; s2 += sB[r][w2]; }
        float mu  = s * (1.f/CC);
        float var = s2 * (1.f/CC) - mu*mu;
        float rstd = rsqrtf(var + 1e-5f);
        Y[r][tid] = (xv[r] - mu) * rstd * gv + bv;
    }
    __syncthreads();

    float acc[8][3];
#pragma unroll
    for (int r = 0; r < 8; r++)
#pragma unroll
        for (int j = 0; j < 3; j++) acc[r][j] = 0.f;

    for (int c = 0; c < CC; c++) {
        float y8[8];
#pragma unroll
        for (int r = 0; r < 8; r++) y8[r] = Y[r][c];
#pragma unroll
        for (int j = 0; j < 3; j++) {
            float wv = g_wti[c*E3 + j*256 + tid];
#pragma unroll
            for (int r = 0; r < 8; r++) acc[r][j] += y8[r]*wv;
        }
    }
#pragma unroll
    for (int r = 0; r < 8; r++)
#pragma unroll
        for (int j = 0; j < 3; j++)
            g_z[(row0 + r)*E3 + j*256 + tid] = acc[r][j];
}

// ---------------- windowed attention: Gram sharing + P aggregation -------
__global__ __launch_bounds__(256) void k_attn(const float* __restrict__ inb) {
    extern __shared__ float sm[];
    float* Gm  = sm;                  // [RB][GSS]
    float* Pm  = Gm + SM_G;           // [RB][GSS]; first part aliased as Zk
    float* ZA  = Pm + SM_G;           // [RB][RS] : Zq then Zv
    float* Us  = ZA + RB*RS;          // [RB]
    float* Wvs = Us + RB;             // [RB]
    float* Hn  = Wvs + RB;            // [WINN]
    float* bqS = Hn + WINN;           // [64]
    float* bkS = bqS + 64;            // [64]
    float* c0S = bkS + 64;            // [1]
    float* Zk  = Pm;                  // alias (dead before P is zeroed)

    int tid = threadIdx.x;
    int g = blockIdx.x, h = blockIdx.y, v = blockIdx.z;
    int l0 = g * WPB;

    if (tid < WINN)
        Hn[tid] = 0.5f*(1.f - cosf(6.283185307179586f*(float)tid/127.f));
    if (tid < 64)  bqS[tid] = inb[h*64 + tid];
    if (tid >= 64 && tid < 128) bkS[tid-64] = inb[CC + h*64 + (tid-64)];

    // load Zq -> ZA, Zk -> Pm
    for (int i = tid; i < RB*64; i += 256) {
        int r = i >> 6, j = i & 63;
        int tp = l0 + r;
        float aq = 0.f, ak = 0.f;
        if (tp >= PADN && tp < PADN + TT) {
            int src = v ? ((tp - PADN - SHIFTN + TT) & (TT-1)) : (tp - PADN);
            aq = g_z[src*E3 + h*64 + j];
            ak = g_z[src*E3 + CC + h*64 + j];
        }
        ZA[r*RS + j] = aq;
        Zk[r*RS + j] = ak;
    }
    __syncthreads();

    // G[a][b] = sum_d Zq[a][d]*Zk[b][d], 4x4 tiles
    for (int idx = tid; idx < 34*34; idx += 256) {
        int ta = idx / 34, tb = idx - ta*34;
        int a0 = ta*4, b0 = tb*4;
        float acc[4][4];
#pragma unroll
        for (int i = 0; i < 4; i++)
#pragma unroll
            for (int i2 = 0; i2 < 4; i2++) acc[i][i2] = 0.f;
        for (int j = 0; j < 64; j += 4) {
            float4 qa[4], kb[4];
#pragma unroll
            for (int i = 0; i < 4; i++) {
                qa[i] = *(const float4*)&ZA[(a0+i)*RS + j];
                kb[i] = *(const float4*)&Zk[(b0+i)*RS + j];
            }
#pragma unroll
            for (int i = 0; i < 4; i++)
#pragma unroll
                for (int i2 = 0; i2 < 4; i2++)
                    acc[i][i2] += qa[i].x*kb[i2].x + qa[i].y*kb[i2].y
                                + qa[i].z*kb[i2].z + qa[i].w*kb[i2].w;
        }
#pragma unroll
        for (int i = 0; i < 4; i++)
#pragma unroll
            for (int i2 = 0; i2 < 4; i2++)
                Gm[(a0+i)*GSS + b0+i2] = acc[i][i2];
    }
    // u[a] = Zq[a].bk ; w[b] = bq.Zk[b]
    if (tid < RB) {
        float su = 0.f, sw = 0.f;
        for (int j = 0; j < 64; j++) {
            su += ZA[tid*RS + j]*bkS[j];
            sw += bqS[j]*Zk[tid*RS + j];
        }
        Us[tid] = su; Wvs[tid] = sw;
    }
    if (tid == 255) {
        float c0 = 0.f;
        for (int j = 0; j < 64; j++) c0 += bqS[j]*bkS[j];
        c0S[0] = c0;
    }
    __syncthreads();

    // zero P, load Zv -> ZA (Zq/Zk dead now)
    for (int i = tid; i < SM_G; i += 256) Pm[i] = 0.f;
    for (int i = tid; i < RB*64; i += 256) {
        int r = i >> 6, j = i & 63;
        int tp = l0 + r;
        float av = 0.f;
        if (tp >= PADN && tp < PADN + TT) {
            int src = v ? ((tp - PADN - SHIFTN + TT) & (TT-1)) : (tp - PADN);
            av = g_z[src*E3 + 2*CC + h*64 + j];
        }
        ZA[r*RS + j] = av;
    }
    __syncthreads();

    // per-window: scores from G, softmax, accumulate P
    int qi = tid >> 1, half = tid & 1;
    float hq = Hn[qi];
    float c0 = c0S[0];
    for (int dl = 0; dl < WPB; dl++) {
        int l = l0 + dl;
        if (l < LW) {
            int a = dl + qi;
            float base = hq*Us[a] + c0;
            const float* grow = &Gm[a*GSS + dl + half*64];
            const float* wrow = &Wvs[dl + half*64];
            const float* hrow = &Hn[half*64];
            float sc[64];
            float m = -1e30f;
#pragma unroll
            for (int j = 0; j < 64; j++) {
                float hk = hrow[j];
                float s = 0.125f*(hq*hk*grow[j] + hk*wrow[j] + base);
                sc[j] = s;
                m = fmaxf(m, s);
            }
            m = fmaxf(m, __shfl_xor_sync(0xffffffffu, m, 1));
            float sum = 0.f;
#pragma unroll
            for (int j = 0; j < 64; j++) {
                float e = __expf(sc[j] - m);
                sc[j] = e; sum += e;
            }
            sum += __shfl_xor_sync(0xffffffffu, sum, 1);
            float inv = 1.f/sum;
            float* prow = &Pm[a*GSS + dl + half*64];
#pragma unroll
            for (int j = 0; j < 64; j++)
                prow[j] += sc[j]*inv*hrow[j];
        }
        __syncthreads();
    }

    // PV: acc[a][jd] = sum_b P[a][b]*Zv[b][jd] ; atomic scatter to g_acc
    for (int idx = tid; idx < 34*16; idx += 256) {
        int ta = idx >> 4, tj = idx & 15;
        int a0 = ta*4, j0 = tj*4;
        float acc[4][4];
#pragma unroll
        for (int i = 0; i < 4; i++)
#pragma unroll
            for (int i2 = 0; i2 < 4; i2++) acc[i][i2] = 0.f;
        for (int b = 0; b < 135; b++) {
            float4 vv = *(const float4*)&ZA[b*RS + j0];
            float pv[4];
#pragma unroll
            for (int i = 0; i < 4; i++) pv[i] = Pm[(a0+i)*GSS + b];
#pragma unroll
            for (int i = 0; i < 4; i++) {
                acc[i][0] += pv[i]*vv.x;
                acc[i][1] += pv[i]*vv.y;
                acc[i][2] += pv[i]*vv.z;
                acc[i][3] += pv[i]*vv.w;
            }
        }
#pragma unroll
        for (int i = 0; i < 4; i++) {
            int a = a0 + i;
            int tp = l0 + a;
            if (a < 135 && tp < TPP) {
                float* dst = &g_acc[((size_t)v*TPP + tp)*CC + h*64 + j0];
#pragma unroll
                for (int i2 = 0; i2 < 4; i2++)
                    atomicAdd(&dst[i2], acc[i][i2]);
            }
        }
    }
}

// ---------------- finalize: combine variants + out-proj + proj -----------
__global__ __launch_bounds__(256) void k_finalize(const float* __restrict__ inb,
                                                  const float* __restrict__ ob,
                                                  const float* __restrict__ pb) {
    __shared__ float U[8][CC];
    __shared__ float Y2[8][CC];
    __shared__ float bb[8];
    int tid = threadIdx.x;
    int t0 = blockIdx.x * 8;
    float bvv = inb[2*CC + tid];

#pragma unroll
    for (int r = 0; r < 8; r++) {
        int t = t0 + r;
        float cm = cntf(t);
        float am = g_acc[(size_t)(t + PADN)*CC + tid];
        float pm = (am + cm*bvv) / (cm + 1e-6f);
        int tau = (t + SHIFTN) & (TT-1);
        float cs = cntf(tau);
        float as = g_acc[(size_t)TPP*CC + (size_t)(tau + PADN)*CC + tid];
        float ps = (as + cs*bvv) / (cs + 1e-6f);
        U[r][tid] = 0.5f*(pm + ps);
        if (tid == 0)
            bb[r] = 0.5f*(cm/(cm + 1e-6f) + cs/(cs + 1e-6f));
    }
    __syncthreads();

    float acc[8];
#pragma unroll
    for (int r = 0; r < 8; r++) acc[r] = 0.f;
    for (int c = 0; c < CC; c++) {
        float w = g_wto[c*CC + tid];
#pragma unroll
        for (int r = 0; r < 8; r++) acc[r] += U[r][c]*w;
    }
    float obv = ob[tid];
    __syncthreads();
#pragma unroll
    for (int r = 0; r < 8; r++) Y2[r][tid] = acc[r] + bb[r]*obv;
    __syncthreads();

#pragma unroll
    for (int r = 0; r < 8; r++) acc[r] = 0.f;
    for (int c = 0; c < CC; c++) {
        float w = g_wtp[c*CC + tid];
#pragma unroll
        for (int r = 0; r < 8; r++) acc[r] += Y2[r][c]*w;
    }
    float pbv = pb[tid];
    float colpart = 0.f;
#pragma unroll
    for (int r = 0; r < 8; r++) {
        float yp = acc[r] + pbv;
        g_y[(size_t)(t0 + r)*CC + tid] = yp;
        colpart += yp;
    }
    atomicAdd(&g_colsum[tid], colpart);
}

// ---------------- SE gate ----------------
__global__ __launch_bounds__(256) void k_se(const float* __restrict__ w1,
                                            const float* __restrict__ w2) {
    __shared__ float s[CC], s1[16];
    int tid = threadIdx.x;
    s[tid] = g_colsum[tid] * (1.f/(float)TT);
    __syncthreads();
    if (tid < 16) {
        float a = 0.f;
        for (int c = 0; c < CC; c++) a += s[c]*w1[tid*CC + c];
        s1[tid] = fmaxf(a, 0.f);
    }
    __syncthreads();
    float a = 0.f;
#pragma unroll
    for (int j = 0; j < 16; j++) a += s1[j]*w2[tid*16 + j];
    g_segate[tid] = 1.f/(1.f + __expf(-a));
}

// ---------------- residual + gate ----------------
__global__ void k_out(const float* __restrict__ x, float* __restrict__ out) {
    int i = blockIdx.x*256 + threadIdx.x;
    out[i] = x[i] + g_y[i]*g_segate[i & 255];
}

extern "C" void kernel_launch(void* const* d_in, const int* in_sizes, int n_in,
                              void* d_out, int out_size) {
    const float* x  = (const float*)d_in[0];
    const float* lg = (const float*)d_in[1];
    const float* lb = (const float*)d_in[2];
    const float* wi = (const float*)d_in[3];
    const float* ib = (const float*)d_in[4];
    const float* wo = (const float*)d_in[5];
    const float* ob = (const float*)d_in[6];
    const float* wp = (const float*)d_in[7];
    const float* pb = (const float*)d_in[8];
    const float* w1 = (const float*)d_in[9];
    const float* w2 = (const float*)d_in[10];
    float* out = (float*)d_out;

    cudaFuncSetAttribute(k_attn, cudaFuncAttributeMaxDynamicSharedMemorySize,
                         SMEM_BYTES);

    k_zero<<<2300, 256>>>();
    k_transpose<<<768, 256>>>(wi, wo, wp);
    k_ln_z<<<128, 256>>>(x, lg, lb);
    k_attn<<<dim3(128, 4, 2), 256, SMEM_BYTES>>>(ib);
    k_finalize<<<128, 256>>>(ib, ob, pb);
    k_se<<<1, 256>>>(w1, w2);
    k_out<<<1024, 256>>>(x, out);
}

// round 3
// speedup vs baseline: 1.3600x; 1.3600x over previous
#include <cuda_runtime.h>
#include <cuda_bf16.h>

#define TT    1024
#define CC    256
#define E3    768
#define WINN  128
#define PADN  63
#define TPP   1150
#define LW    1023
#define SHIFTN 64
#define WPB   8
#define RB    136
#define RS    68
#define GSS   137
#define ATHREADS 512

#define SM_G   (RB*GSS)
#define SM_ALL (2*SM_G + RB*RS + 2*RB + WINN + 2*64 + 1)
#define SMEM_BYTES (SM_ALL*4)

__device__ float g_z[TT*E3];
__device__ float g_acc[2*TPP*CC];
__device__ float g_wti[CC*E3];
__device__ float g_wto[CC*CC];
__device__ float g_wtp[CC*CC];
__device__ float g_y[TT*CC];
__device__ float g_colsum[CC];
__device__ float g_segate[CC];

__device__ __forceinline__ float cntf(int t) {
    int tp = t + PADN;
    int lmin = tp - 127; if (lmin < 0) lmin = 0;
    int lmax = tp;       if (lmax > 1022) lmax = 1022;
    return (float)(lmax - lmin + 1);
}

__global__ void k_zero() {
    int i = blockIdx.x * 256 + threadIdx.x;
    if (i < 2*TPP*CC) g_acc[i] = 0.f;
    if (i < CC) g_colsum[i] = 0.f;
}

__global__ void k_transpose(const float* __restrict__ wi,
                            const float* __restrict__ wo,
                            const float* __restrict__ wp) {
    int idx = blockIdx.x * 256 + threadIdx.x;
    if (idx < E3*CC) {
        int e = idx >> 8, c = idx & 255;
        g_wti[c*E3 + e] = wi[idx];
    }
    if (idx < CC*CC) {
        int e = idx >> 8, c = idx & 255;
        g_wto[c*CC + e] = wo[idx];
        g_wtp[c*CC + e] = wp[idx];
    }
}

// ---------------- LayerNorm + z = LN(x) @ Win^T (bias hoisted) -----------
__global__ __launch_bounds__(256) void k_ln_z(const float* __restrict__ x,
                                              const float* __restrict__ lg,
                                              const float* __restrict__ lb) {
    __shared__ float Y[8][CC];
    __shared__ float sA[8][8], sB[8][8];
    int tid = threadIdx.x, warp = tid >> 5, lane = tid & 31;
    int row0 = blockIdx.x * 8;

    float gv = lg[tid], bv = lb[tid];
    float xv[8];
#pragma unroll
    for (int r = 0; r < 8; r++) {
        float v = x[(row0 + r)*CC + tid];
        xv[r] = v;
        float s = v, s2 = v*v;
#pragma unroll
        for (int o = 16; o; o >>= 1) {
            s  += __shfl_xor_sync(0xffffffffu, s, o);
            s2 += __shfl_xor_sync(0xffffffffu, s2, o);
        }
        if (lane == 0) { sA[r][warp] = s; sB[r][warp] = s2; }
    }
    __syncthreads();
#pragma unroll
    for (int r = 0; r < 8; r++) {
        float s = 0.f, s2 = 0.f;
#pragma unroll
        for (int w2 = 0; w2 < 8; w2++) { s += sA[r][w2]; s2 += sB[r][w2]; }
        float mu  = s * (1.f/CC);
        float var = s2 * (1.f/CC) - mu*mu;
        float rstd = rsqrtf(var + 1e-5f);
        Y[r][tid] = (xv[r] - mu) * rstd * gv + bv;
    }
    __syncthreads();

    float acc[8][3];
#pragma unroll
    for (int r = 0; r < 8; r++)
#pragma unroll
        for (int j = 0; j < 3; j++) acc[r][j] = 0.f;

    for (int c = 0; c < CC; c++) {
        float y8[8];
#pragma unroll
        for (int r = 0; r < 8; r++) y8[r] = Y[r][c];
#pragma unroll
        for (int j = 0; j < 3; j++) {
            float wv = g_wti[c*E3 + j*256 + tid];
#pragma unroll
            for (int r = 0; r < 8; r++) acc[r][j] += y8[r]*wv;
        }
    }
#pragma unroll
    for (int r = 0; r < 8; r++)
#pragma unroll
        for (int j = 0; j < 3; j++)
            g_z[(row0 + r)*E3 + j*256 + tid] = acc[r][j];
}

// ---------------- windowed attention: Gram sharing + P aggregation -------
__global__ __launch_bounds__(ATHREADS) void k_attn(const float* __restrict__ inb) {
    extern __shared__ float sm[];
    float* Gm  = sm;                  // [RB][GSS]
    float* Pm  = Gm + SM_G;           // [RB][GSS]; aliased as Zk early
    float* ZA  = Pm + SM_G;           // [RB][RS] : Zq then Zv
    float* Us  = ZA + RB*RS;          // [RB]
    float* Wvs = Us + RB;             // [RB]
    float* Hn  = Wvs + RB;            // [WINN]
    float* bqS = Hn + WINN;           // [64]
    float* bkS = bqS + 64;            // [64]
    float* c0S = bkS + 64;            // [1]
    float* Zk  = Pm;

    int tid = threadIdx.x;
    int g = blockIdx.x, h = blockIdx.y, v = blockIdx.z;
    int l0 = g * WPB;

    if (tid < WINN)
        Hn[tid] = 0.5f*(1.f - cosf(6.283185307179586f*(float)tid/127.f));
    if (tid < 64)  bqS[tid] = inb[h*64 + tid];
    if (tid >= 64 && tid < 128) bkS[tid-64] = inb[CC + h*64 + (tid-64)];

    // load Zq -> ZA, Zk -> Pm
    for (int i = tid; i < RB*64; i += ATHREADS) {
        int r = i >> 6, j = i & 63;
        int tp = l0 + r;
        float aq = 0.f, ak = 0.f;
        if (tp >= PADN && tp < PADN + TT) {
            int src = v ? ((tp - PADN - SHIFTN + TT) & (TT-1)) : (tp - PADN);
            aq = g_z[src*E3 + h*64 + j];
            ak = g_z[src*E3 + CC + h*64 + j];
        }
        ZA[r*RS + j] = aq;
        Zk[r*RS + j] = ak;
    }
    __syncthreads();

    // G[a][b] = sum_d Zq[a][d]*Zk[b][d]; 4x4 tiles with rows strided by 34
    // (lane-adjacent threads read consecutive rows -> conflict-free LDS.128)
    for (int idx = tid; idx < 34*34; idx += ATHREADS) {
        int ta = idx / 34, tb = idx - ta*34;
        float acc[4][4];
#pragma unroll
        for (int i = 0; i < 4; i++)
#pragma unroll
            for (int i2 = 0; i2 < 4; i2++) acc[i][i2] = 0.f;
        for (int j = 0; j < 64; j += 4) {
            float4 qa[4], kb[4];
#pragma unroll
            for (int i = 0; i < 4; i++) {
                qa[i] = *(const float4*)&ZA[(ta + 34*i)*RS + j];
                kb[i] = *(const float4*)&Zk[(tb + 34*i)*RS + j];
            }
#pragma unroll
            for (int i = 0; i < 4; i++)
#pragma unroll
                for (int i2 = 0; i2 < 4; i2++)
                    acc[i][i2] += qa[i].x*kb[i2].x + qa[i].y*kb[i2].y
                                + qa[i].z*kb[i2].z + qa[i].w*kb[i2].w;
        }
#pragma unroll
        for (int i = 0; i < 4; i++)
#pragma unroll
            for (int i2 = 0; i2 < 4; i2++)
                Gm[(ta + 34*i)*GSS + tb + 34*i2] = acc[i][i2];
    }
    // u[a] = Zq[a].bk ; w[b] = bq.Zk[b]
    if (tid < RB) {
        float su = 0.f, sw = 0.f;
        for (int j = 0; j < 64; j++) {
            su += ZA[tid*RS + j]*bkS[j];
            sw += bqS[j]*Zk[tid*RS + j];
        }
        Us[tid] = su; Wvs[tid] = sw;
    }
    if (tid == ATHREADS-1) {
        float c0 = 0.f;
        for (int j = 0; j < 64; j++) c0 += bqS[j]*bkS[j];
        c0S[0] = c0;
    }
    __syncthreads();

    // zero P, load Zv -> ZA (Zq/Zk dead now)
    for (int i = tid; i < SM_G; i += ATHREADS) Pm[i] = 0.f;
    for (int i = tid; i < RB*64; i += ATHREADS) {
        int r = i >> 6, j = i & 63;
        int tp = l0 + r;
        float av = 0.f;
        if (tp >= PADN && tp < PADN + TT) {
            int src = v ? ((tp - PADN - SHIFTN + TT) & (TT-1)) : (tp - PADN);
            av = g_z[src*E3 + 2*CC + h*64 + j];
        }
        ZA[r*RS + j] = av;
    }
    __syncthreads();

    // per-window: scores from G, softmax (no max pass; scores are O(1)),
    // accumulate P. 4 threads per q-row, 32 cols each, bank-staggered.
    int qi = tid >> 2, q = tid & 3;
    float hq = Hn[qi];
    float c0 = c0S[0];
    int off = 8*q;
    for (int dl = 0; dl < WPB; dl++) {
        int l = l0 + dl;
        if (l < LW) {
            int a = dl + qi;
            float base = hq*Us[a] + c0;
            const float* grow = &Gm[a*GSS + dl + q*32];
            const float* wrow = &Wvs[dl + q*32];
            const float* hrow = &Hn[q*32];
            float sc[32];
            float sum = 0.f;
#pragma unroll
            for (int jj = 0; jj < 32; jj++) {
                int jr = (jj + off) & 31;
                float hk = hrow[jr];
                float e = __expf(0.125f*(hq*hk*grow[jr] + hk*wrow[jr] + base));
                sc[jj] = e;
                sum += e;
            }
            sum += __shfl_xor_sync(0xffffffffu, sum, 1);
            sum += __shfl_xor_sync(0xffffffffu, sum, 2);
            float inv = 1.f/sum;
            float* prow = &Pm[a*GSS + dl + q*32];
#pragma unroll
            for (int jj = 0; jj < 32; jj++) {
                int jr = (jj + off) & 31;
                prow[jr] += sc[jj]*inv*hrow[jr];
            }
        }
        __syncthreads();
    }

    // PV: acc[a][jd] = sum_b P[a][b]*Zv[b][jd] ; atomic scatter to g_acc
    for (int idx = tid; idx < 34*16; idx += ATHREADS) {
        int ta = idx >> 4, tj = idx & 15;
        int a0 = ta*4, j0 = tj*4;
        float acc[4][4];
#pragma unroll
        for (int i = 0; i < 4; i++)
#pragma unroll
            for (int i2 = 0; i2 < 4; i2++) acc[i][i2] = 0.f;
        for (int b = 0; b < 135; b++) {
            float4 vv = *(const float4*)&ZA[b*RS + j0];
            float pv[4];
#pragma unroll
            for (int i = 0; i < 4; i++) pv[i] = Pm[(a0+i)*GSS + b];
#pragma unroll
            for (int i = 0; i < 4; i++) {
                acc[i][0] += pv[i]*vv.x;
                acc[i][1] += pv[i]*vv.y;
                acc[i][2] += pv[i]*vv.z;
                acc[i][3] += pv[i]*vv.w;
            }
        }
#pragma unroll
        for (int i = 0; i < 4; i++) {
            int a = a0 + i;
            int tp = l0 + a;
            if (a < 135 && tp < TPP) {
                float* dst = &g_acc[((size_t)v*TPP + tp)*CC + h*64 + j0];
#pragma unroll
                for (int i2 = 0; i2 < 4; i2++)
                    atomicAdd(&dst[i2], acc[i][i2]);
            }
        }
    }
}

// ---------------- finalize: combine variants + out-proj + proj -----------
__global__ __launch_bounds__(256) void k_finalize(const float* __restrict__ inb,
                                                  const float* __restrict__ ob,
                                                  const float* __restrict__ pb) {
    __shared__ float U[8][CC];
    __shared__ float Y2[8][CC];
    __shared__ float bb[8];
    int tid = threadIdx.x;
    int t0 = blockIdx.x * 8;
    float bvv = inb[2*CC + tid];

#pragma unroll
    for (int r = 0; r < 8; r++) {
        int t = t0 + r;
        float cm = cntf(t);
        float am = g_acc[(size_t)(t + PADN)*CC + tid];
        float pm = (am + cm*bvv) / (cm + 1e-6f);
        int tau = (t + SHIFTN) & (TT-1);
        float cs = cntf(tau);
        float as = g_acc[(size_t)TPP*CC + (size_t)(tau + PADN)*CC + tid];
        float ps = (as + cs*bvv) / (cs + 1e-6f);
        U[r][tid] = 0.5f*(pm + ps);
        if (tid == 0)
            bb[r] = 0.5f*(cm/(cm + 1e-6f) + cs/(cs + 1e-6f));
    }
    __syncthreads();

    float acc[8];
#pragma unroll
    for (int r = 0; r < 8; r++) acc[r] = 0.f;
    for (int c = 0; c < CC; c++) {
        float w = g_wto[c*CC + tid];
#pragma unroll
        for (int r = 0; r < 8; r++) acc[r] += U[r][c]*w;
    }
    float obv = ob[tid];
    __syncthreads();
#pragma unroll
    for (int r = 0; r < 8; r++) Y2[r][tid] = acc[r] + bb[r]*obv;
    __syncthreads();

#pragma unroll
    for (int r = 0; r < 8; r++) acc[r] = 0.f;
    for (int c = 0; c < CC; c++) {
        float w = g_wtp[c*CC + tid];
#pragma unroll
        for (int r = 0; r < 8; r++) acc[r] += Y2[r][c]*w;
    }
    float pbv = pb[tid];
    float colpart = 0.f;
#pragma unroll
    for (int r = 0; r < 8; r++) {
        float yp = acc[r] + pbv;
        g_y[(size_t)(t0 + r)*CC + tid] = yp;
        colpart += yp;
    }
    atomicAdd(&g_colsum[tid], colpart);
}

// ---------------- SE gate ----------------
__global__ __launch_bounds__(256) void k_se(const float* __restrict__ w1,
                                            const float* __restrict__ w2) {
    __shared__ float s[CC], s1[16];
    int tid = threadIdx.x;
    s[tid] = g_colsum[tid] * (1.f/(float)TT);
    __syncthreads();
    if (tid < 16) {
        float a = 0.f;
        for (int c = 0; c < CC; c++) a += s[c]*w1[tid*CC + c];
        s1[tid] = fmaxf(a, 0.f);
    }
    __syncthreads();
    float a = 0.f;
#pragma unroll
    for (int j = 0; j < 16; j++) a += s1[j]*w2[tid*16 + j];
    g_segate[tid] = 1.f/(1.f + __expf(-a));
}

// ---------------- residual + gate ----------------
__global__ void k_out(const float* __restrict__ x, float* __restrict__ out) {
    int i = blockIdx.x*256 + threadIdx.x;
    out[i] = x[i] + g_y[i]*g_segate[i & 255];
}

extern "C" void kernel_launch(void* const* d_in, const int* in_sizes, int n_in,
                              void* d_out, int out_size) {
    const float* x  = (const float*)d_in[0];
    const float* lg = (const float*)d_in[1];
    const float* lb = (const float*)d_in[2];
    const float* wi = (const float*)d_in[3];
    const float* ib = (const float*)d_in[4];
    const float* wo = (const float*)d_in[5];
    const float* ob = (const float*)d_in[6];
    const float* wp = (const float*)d_in[7];
    const float* pb = (const float*)d_in[8];
    const float* w1 = (const float*)d_in[9];
    const float* w2 = (const float*)d_in[10];
    float* out = (float*)d_out;

    cudaFuncSetAttribute(k_attn, cudaFuncAttributeMaxDynamicSharedMemorySize,
                         SMEM_BYTES);

    k_zero<<<2300, 256>>>();
    k_transpose<<<768, 256>>>(wi, wo, wp);
    k_ln_z<<<128, 256>>>(x, lg, lb);
    k_attn<<<dim3(128, 4, 2), ATHREADS, SMEM_BYTES>>>(ib);
    k_finalize<<<128, 256>>>(ib, ob, pb);
    k_se<<<1, 256>>>(w1, w2);
    k_out<<<1024, 256>>>(x, out);
}

// round 5
// speedup vs baseline: 1.5275x; 1.1232x over previous
#include <cuda_runtime.h>
#include <cuda_bf16.h>
#include <cstdint>
#include <stdint.h>

#define TT    1024
#define CC    256
#define E3    768
#define WINN  128
#define PADN  63
#define TPP   1150
#define LW    1023
#define SHIFTN 64
#define WPB   8
#define RB    136
#define GST   138
#define ATHREADS 512

// smem layout (bytes)
#define OFF_ZQ  37536          // Gm: 136*138 bf16
#define OFF_ZK  56032          // Zq: 136*34 u32
#define OFF_F   74528          // Zk: 136*34 u32
#define SMEM_BYTES 80768

// scale folded: 0.125 * log2(e)
#define SCC 0.18033688011112042f

__device__ float g_z[TT*E3];
__device__ float g_acc[2*TPP*CC];
__device__ float g_wti[CC*E3];
__device__ float g_wto[CC*CC];
__device__ float g_wtp[CC*CC];
__device__ float g_y[TT*CC];
__device__ float g_colsum[CC];
__device__ float g_segate[CC];

__device__ __forceinline__ float2 b2f(uint32_t u) {
    float2 r;
    r.x = __uint_as_float(u << 16);
    r.y = __uint_as_float(u & 0xffff0000u);
    return r;
}
__device__ __forceinline__ uint32_t f2b2(float a, float b) {
    __nv_bfloat162 t = __floats2bfloat162_rn(a, b);
    return *(uint32_t*)&t;
}
__device__ __forceinline__ float b2f1(__nv_bfloat16 h) {
    return __uint_as_float(((uint32_t)*(unsigned short*)&h) << 16);
}
__device__ __forceinline__ __nv_bfloat162 u2b(uint32_t u) {
    return *(__nv_bfloat162*)&u;
}

__device__ __forceinline__ float cntf(int t) {
    int tp = t + PADN;
    int lmin = tp - 127; if (lmin < 0) lmin = 0;
    int lmax = tp;       if (lmax > 1022) lmax = 1022;
    return (float)(lmax - lmin + 1);
}

__global__ void k_zero() {
    int i = blockIdx.x * 256 + threadIdx.x;
    if (i < 2*TPP*CC) g_acc[i] = 0.f;
    if (i < CC) g_colsum[i] = 0.f;
}

__global__ void k_transpose(const float* __restrict__ wi,
                            const float* __restrict__ wo,
                            const float* __restrict__ wp) {
    int idx = blockIdx.x * 256 + threadIdx.x;
    if (idx < E3*CC) {
        int e = idx >> 8, c = idx & 255;
        g_wti[c*E3 + e] = wi[idx];
    }
    if (idx < CC*CC) {
        int e = idx >> 8, c = idx & 255;
        g_wto[c*CC + e] = wo[idx];
        g_wtp[c*CC + e] = wp[idx];
    }
}

// ---------------- LayerNorm + z = LN(x) @ Win^T (bias hoisted) -----------
__global__ __launch_bounds__(256) void k_ln_z(const float* __restrict__ x,
                                              const float* __restrict__ lg,
                                              const float* __restrict__ lb) {
    __shared__ float Y[8][CC];
    __shared__ float sA[8][8], sB[8][8];
    int tid = threadIdx.x, warp = tid >> 5, lane = tid & 31;
    int row0 = blockIdx.x * 8;

    float gv = lg[tid], bv = lb[tid];
    float xv[8];
#pragma unroll
    for (int r = 0; r < 8; r++) {
        float v = x[(row0 + r)*CC + tid];
        xv[r] = v;
        float s = v, s2 = v*v;
#pragma unroll
        for (int o = 16; o; o >>= 1) {
            s  += __shfl_xor_sync(0xffffffffu, s, o);
            s2 += __shfl_xor_sync(0xffffffffu, s2, o);
        }
        if (lane == 0) { sA[r][warp] = s; sB[r][warp] = s2; }
    }
    __syncthreads();
#pragma unroll
    for (int r = 0; r < 8; r++) {
        float s = 0.f, s2 = 0.f;
#pragma unroll
        for (int w2 = 0; w2 < 8; w2++) { s += sA[r][w2]; s2 += sB[r][w2]; }
        float mu  = s * (1.f/CC);
        float var = s2 * (1.f/CC) - mu*mu;
        float rstd = rsqrtf(var + 1e-5f);
        Y[r][tid] = (xv[r] - mu) * rstd * gv + bv;
    }
    __syncthreads();

    float acc[8][3];
#pragma unroll
    for (int r = 0; r < 8; r++)
#pragma unroll
        for (int j = 0; j < 3; j++) acc[r][j] = 0.f;

    for (int c = 0; c < CC; c++) {
        float y8[8];
#pragma unroll
        for (int r = 0; r < 8; r++) y8[r] = Y[r][c];
#pragma unroll
        for (int j = 0; j < 3; j++) {
            float wv = g_wti[c*E3 + j*256 + tid];
#pragma unroll
            for (int r = 0; r < 8; r++) acc[r][j] += y8[r]*wv;
        }
    }
#pragma unroll
    for (int r = 0; r < 8; r++)
#pragma unroll
        for (int j = 0; j < 3; j++)
            g_z[(row0 + r)*E3 + j*256 + tid] = acc[r][j];
}

// ---------------- windowed attention v3: gather-P, bf16, 2 CTAs/SM -------
__global__ __launch_bounds__(ATHREADS, 2) void k_attn(const float* __restrict__ inb) {
    extern __shared__ unsigned char smraw[];
    __nv_bfloat16* Gm = (__nv_bfloat16*)smraw;          // [136][138] bf16; later P
    uint32_t* Zq = (uint32_t*)(smraw + OFF_ZQ);         // [136][34] bf16x2
    uint32_t* Zk = (uint32_t*)(smraw + OFF_ZK);         // [136][34] bf16x2
    float* Fs   = (float*)(smraw + OFF_F);
    float* Us   = Fs;            // [136]  (pre-scaled by SCC)
    float* Wvs  = Fs + 136;      // [136]  (pre-scaled by SCC)
    float* invA = Fs + 272;      // [8][128]
    float* Hn   = Fs + 1296;     // [128]
    float* bqS  = Fs + 1424;     // [64]
    float* bkS  = Fs + 1488;     // [64]
    float* c0S  = Fs + 1552;     // [1]
    uint32_t* Zv = Zq;           // alias (Zq dead after G phase)

    int tid = threadIdx.x;
    int g = blockIdx.x, h = blockIdx.y, v = blockIdx.z;
    int l0 = g * WPB;

    if (tid < 128)
        Hn[tid] = 0.5f*(1.f - cosf(6.283185307179586f*(float)tid/127.f));
    if (tid >= 128 && tid < 192) bqS[tid-128] = inb[h*64 + (tid-128)];
    if (tid >= 192 && tid < 256) bkS[tid-192] = inb[CC + h*64 + (tid-192)];

    // load Zq / Zk (bf16 packed)
    for (int i = tid; i < RB*32; i += ATHREADS) {
        int r = i >> 5, jw = i & 31;
        int tp = l0 + r;
        float2 aq = make_float2(0.f, 0.f), ak = make_float2(0.f, 0.f);
        if (tp >= PADN && tp < PADN + TT) {
            int src = v ? ((tp - PADN - SHIFTN + TT) & (TT-1)) : (tp - PADN);
            const float* zp = &g_z[src*E3 + h*64 + 2*jw];
            aq = *(const float2*)zp;
            ak = *(const float2*)(zp + CC);
        }
        Zq[r*34 + jw] = f2b2(aq.x, aq.y);
        Zk[r*34 + jw] = f2b2(ak.x, ak.y);
    }
    __syncthreads();

    // ---- G (HFMA2, rows strided by 34 to stay conflict-free) ----
    for (int idx = tid; idx < 34*34; idx += ATHREADS) {
        int ta = idx / 34, tb = idx - ta*34;
        __nv_bfloat162 acc2[4][4];
        __nv_bfloat162 z2 = __float2bfloat162_rn(0.f);
#pragma unroll
        for (int i = 0; i < 4; i++)
#pragma unroll
            for (int i2 = 0; i2 < 4; i2++) acc2[i][i2] = z2;
        for (int jw = 0; jw < 32; jw += 2) {
            uint2 A[4], B[4];
#pragma unroll
            for (int i = 0; i < 4; i++) {
                A[i] = *(const uint2*)&Zq[(ta + 34*i)*34 + jw];
                B[i] = *(const uint2*)&Zk[(tb + 34*i)*34 + jw];
            }
#pragma unroll
            for (int i = 0; i < 4; i++)
#pragma unroll
                for (int i2 = 0; i2 < 4; i2++) {
                    acc2[i][i2] = __hfma2(u2b(A[i].x), u2b(B[i2].x), acc2[i][i2]);
                    acc2[i][i2] = __hfma2(u2b(A[i].y), u2b(B[i2].y), acc2[i][i2]);
                }
        }
#pragma unroll
        for (int i = 0; i < 4; i++)
#pragma unroll
            for (int i2 = 0; i2 < 4; i2++) {
                float gf = SCC*(__low2float(acc2[i][i2]) + __high2float(acc2[i][i2]));
                Gm[(ta + 34*i)*GST + tb + 34*i2] = __float2bfloat16_rn(gf);
            }
    }
    // u[a] = SCC * Zq[a].bk ; w[b] = SCC * bq.Zk[b]
    if (tid < 136) {
        float su = 0.f;
        for (int jw = 0; jw < 32; jw++) {
            float2 q2 = b2f(Zq[tid*34 + jw]);
            su += q2.x*bkS[2*jw] + q2.y*bkS[2*jw+1];
        }
        Us[tid] = SCC*su;
    } else if (tid < 272) {
        int r = tid - 136;
        float sw = 0.f;
        for (int jw = 0; jw < 32; jw++) {
            float2 k2 = b2f(Zk[r*34 + jw]);
            sw += k2.x*bqS[2*jw] + k2.y*bqS[2*jw+1];
        }
        Wvs[r] = SCC*sw;
    } else if (tid == 272) {
        float c0 = 0.f;
        for (int j = 0; j < 64; j++) c0 += bqS[j]*bkS[j];
        c0S[0] = SCC*c0;
    }
    __syncthreads();

    // ---- load Zv (overwrites Zq) + pass A: row sums ----
    for (int i = tid; i < RB*32; i += ATHREADS) {
        int r = i >> 5, jw = i & 31;
        int tp = l0 + r;
        float2 av = make_float2(0.f, 0.f);
        if (tp >= PADN && tp < PADN + TT) {
            int src = v ? ((tp - PADN - SHIFTN + TT) & (TT-1)) : (tp - PADN);
            av = *(const float2*)&g_z[src*E3 + 2*CC + h*64 + 2*jw];
        }
        Zv[r*34 + jw] = f2b2(av.x, av.y);
    }
    float c0 = c0S[0];
    for (int rr = tid; rr < 1024; rr += ATHREADS) {
        int dl = rr >> 7, q = rr & 127;
        if (l0 + dl < LW) {
            int a = dl + q;
            float hq = Hn[q];
            float base = fmaf(hq, Us[a], c0);
            const __nv_bfloat16* grow = &Gm[a*GST + dl];
            const float* wrow = &Wvs[dl];
            float sum = 0.f;
#pragma unroll 4
            for (int k = 0; k < 128; k++) {
                float gv = b2f1(grow[k]);
                float s = fmaf(fmaf(hq, gv, wrow[k]), Hn[k], base);
                sum += exp2f(s);
            }
            invA[dl*128 + q] = 1.f/sum;
        }
    }
    __syncthreads();

    // ---- pass B: P[a][b] gathered in place over G ----
    for (int a = tid >> 2; a < 136; a += 128) {
        float gq[8], base[8], iv[8];
        float ua = Us[a];
#pragma unroll
        for (int dl = 0; dl < 8; dl++) {
            int qd = a - dl;
            bool va = (qd >= 0 && qd < 128);
            float hq = va ? Hn[qd] : 0.f;
            gq[dl] = hq;
            base[dl] = fmaf(hq, ua, c0);
            iv[dl] = (va && (l0 + dl) < LW) ? invA[dl*128 + qd] : 0.f;
        }
        int q4 = tid & 3;
        for (int jj = 0; jj < 34; jj++) {
            int b = q4 + 4*jj;
            float gval = b2f1(Gm[a*GST + b]);
            float wb = Wvs[b];
            float p = 0.f;
#pragma unroll
            for (int dl = 0; dl < 8; dl++) {
                int kd = b - dl;
                if (kd >= 0 && kd < 128) {
                    float hk = Hn[kd];
                    float s = fmaf(fmaf(gq[dl], gval, wb), hk, base[dl]);
                    p = fmaf(hk*iv[dl], exp2f(s), p);
                }
            }
            Gm[a*GST + b] = __float2bfloat16_rn(p);
        }
    }
    __syncthreads();

    // ---- PV: acc[a][j] = sum_b P[a][b]*Zv[b][j]; scatter to g_acc ----
    for (int idx = tid; idx < 34*16; idx += ATHREADS) {
        int ta = idx >> 4, tj = idx & 15;
        int a0 = ta*4, j0 = tj*4;
        float acc[4][4];
#pragma unroll
        for (int i = 0; i < 4; i++)
#pragma unroll
            for (int c = 0; c < 4; c++) acc[i][c] = 0.f;
        for (int bw = 0; bw < 68; bw++) {
            uint2 V0 = *(const uint2*)&Zv[(2*bw)*34 + (j0 >> 1)];
            uint2 V1 = *(const uint2*)&Zv[(2*bw+1)*34 + (j0 >> 1)];
            float2 va = b2f(V0.x), vb = b2f(V0.y);
            float2 wa = b2f(V1.x), wb = b2f(V1.y);
#pragma unroll
            for (int i = 0; i < 4; i++) {
                float2 pp = b2f(*(const uint32_t*)&Gm[(a0+i)*GST + 2*bw]);
                acc[i][0] = fmaf(pp.x, va.x, fmaf(pp.y, wa.x, acc[i][0]));
                acc[i][1] = fmaf(pp.x, va.y, fmaf(pp.y, wa.y, acc[i][1]));
                acc[i][2] = fmaf(pp.x, vb.x, fmaf(pp.y, wb.x, acc[i][2]));
                acc[i][3] = fmaf(pp.x, vb.y, fmaf(pp.y, wb.y, acc[i][3]));
            }
        }
#pragma unroll
        for (int i = 0; i < 4; i++) {
            int tp = l0 + a0 + i;
            if (tp < TPP) {
                float* dst = &g_acc[((size_t)v*TPP + tp)*CC + h*64 + j0];
#pragma unroll
                for (int c = 0; c < 4; c++)
                    atomicAdd(&dst[c], acc[i][c]);
            }
        }
    }
}

// ---------------- finalize: combine variants + out-proj + proj -----------
__global__ __launch_bounds__(256) void k_finalize(const float* __restrict__ inb,
                                                  const float* __restrict__ ob,
                                                  const float* __restrict__ pb) {
    __shared__ float U[8][CC];
    __shared__ float Y2[8][CC];
    __shared__ float bb[8];
    int tid = threadIdx.x;
    int t0 = blockIdx.x * 8;
    float bvv = inb[2*CC + tid];

#pragma unroll
    for (int r = 0; r < 8; r++) {
        int t = t0 + r;
        float cm = cntf(t);
        float am = g_acc[(size_t)(t + PADN)*CC + tid];
        float pm = (am + cm*bvv) / (cm + 1e-6f);
        int tau = (t + SHIFTN) & (TT-1);
        float cs = cntf(tau);
        float as = g_acc[(size_t)TPP*CC + (size_t)(tau + PADN)*CC + tid];
        float ps = (as + cs*bvv) / (cs + 1e-6f);
        U[r][tid] = 0.5f*(pm + ps);
        if (tid == 0)
            bb[r] = 0.5f*(cm/(cm + 1e-6f) + cs/(cs + 1e-6f));
    }
    __syncthreads();

    float acc[8];
#pragma unroll
    for (int r = 0; r < 8; r++) acc[r] = 0.f;
    for (int c = 0; c < CC; c++) {
        float w = g_wto[c*CC + tid];
#pragma unroll
        for (int r = 0; r < 8; r++) acc[r] += U[r][c]*w;
    }
    float obv = ob[tid];
    __syncthreads();
#pragma unroll
    for (int r = 0; r < 8; r++) Y2[r][tid] = acc[r] + bb[r]*obv;
    __syncthreads();

#pragma unroll
    for (int r = 0; r < 8; r++) acc[r] = 0.f;
    for (int c = 0; c < CC; c++) {
        float w = g_wtp[c*CC + tid];
#pragma unroll
        for (int r = 0; r < 8; r++) acc[r] += Y2[r][c]*w;
    }
    float pbv = pb[tid];
    float colpart = 0.f;
#pragma unroll
    for (int r = 0; r < 8; r++) {
        float yp = acc[r] + pbv;
        g_y[(size_t)(t0 + r)*CC + tid] = yp;
        colpart += yp;
    }
    atomicAdd(&g_colsum[tid], colpart);
}

// ---------------- SE gate ----------------
__global__ __launch_bounds__(256) void k_se(const float* __restrict__ w1,
                                            const float* __restrict__ w2) {
    __shared__ float s[CC], s1[16];
    int tid = threadIdx.x;
    s[tid] = g_colsum[tid] * (1.f/(float)TT);
    __syncthreads();
    if (tid < 16) {
        float a = 0.f;
        for (int c = 0; c < CC; c++) a += s[c]*w1[tid*CC + c];
        s1[tid] = fmaxf(a, 0.f);
    }
    __syncthreads();
    float a = 0.f;
#pragma unroll
    for (int j = 0; j < 16; j++) a += s1[j]*w2[tid*16 + j];
    g_segate[tid] = 1.f/(1.f + __expf(-a));
}

// ---------------- residual + gate ----------------
__global__ void k_out(const float* __restrict__ x, float* __restrict__ out) {
    int i = blockIdx.x*256 + threadIdx.x;
    out[i] = x[i] + g_y[i]*g_segate[i & 255];
}

extern "C" void kernel_launch(void* const* d_in, const int* in_sizes, int n_in,
                              void* d_out, int out_size) {
    const float* x  = (const float*)d_in[0];
    const float* lg = (const float*)d_in[1];
    const float* lb = (const float*)d_in[2];
    const float* wi = (const float*)d_in[3];
    const float* ib = (const float*)d_in[4];
    const float* wo = (const float*)d_in[5];
    const float* ob = (const float*)d_in[6];
    const float* wp = (const float*)d_in[7];
    const float* pb = (const float*)d_in[8];
    const float* w1 = (const float*)d_in[9];
    const float* w2 = (const float*)d_in[10];
    float* out = (float*)d_out;

    cudaFuncSetAttribute(k_attn, cudaFuncAttributeMaxDynamicSharedMemorySize,
                         SMEM_BYTES);

    k_zero<<<2300, 256>>>();
    k_transpose<<<768, 256>>>(wi, wo, wp);
    k_ln_z<<<128, 256>>>(x, lg, lb);
    k_attn<<<dim3(128, 4, 2), ATHREADS, SMEM_BYTES>>>(ib);
    k_finalize<<<128, 256>>>(ib, ob, pb);
    k_se<<<1, 256>>>(w1, w2);
    k_out<<<1024, 256>>>(x, out);
}

// round 7
// speedup vs baseline: 1.8824x; 1.2323x over previous
#include <cuda_runtime.h>
#include <cuda_bf16.h>
#include <cstdint>
#include <stdint.h>

#define TT    1024
#define CC    256
#define E3    768
#define WINN  128
#define PADN  63
#define TPP   1150
#define LW    1023
#define SHIFTN 64
#define WPB   8
#define RB    136
#define GST   138
#define ATHREADS 512

// smem layout (bytes)
#define OFF_ZQ  37536          // Gm: 136*138 bf16
#define OFF_ZK  56032          // Zq: 136*34 u32
#define OFF_F   74528          // Zk: 136*34 u32
#define SMEM_BYTES 82176

// Fs-region offsets (float slots)
#define F_US    0
#define F_WVS   136
#define F_INVA  272
#define F_HN    1296          // 130 used (+pad)
#define F_BQ    1428
#define F_BK    1492
#define F_C0    1556
#define F_HN2E  1560
#define F_HN2O  1624
#define F_WVB   1688          // 136 bf16 = 68 slots
#define F_HNP   1756          // 144

// scale folded: 0.125 * log2(e)
#define SCC 0.18033688011112042f

__device__ float g_z[TT*E3];
__device__ float g_acc[2*TPP*CC];
__device__ float g_wti[CC*E3];
__device__ float g_wto[CC*CC];
__device__ float g_wtp[CC*CC];
__device__ float g_y[TT*CC];
__device__ float g_colsum[CC];
__device__ float g_segate[CC];

__device__ __forceinline__ float2 b2f(uint32_t u) {
    float2 r;
    r.x = __uint_as_float(u << 16);
    r.y = __uint_as_float(u & 0xffff0000u);
    return r;
}
__device__ __forceinline__ uint32_t f2b2(float a, float b) {
    __nv_bfloat162 t = __floats2bfloat162_rn(a, b);
    return *(uint32_t*)&t;
}
__device__ __forceinline__ float b2f1(__nv_bfloat16 h) {
    return __uint_as_float(((uint32_t)*(unsigned short*)&h) << 16);
}
__device__ __forceinline__ __nv_bfloat162 u2b(uint32_t u) {
    return *(__nv_bfloat162*)&u;
}

__device__ __forceinline__ float cntf(int t) {
    int tp = t + PADN;
    int lmin = tp - 127; if (lmin < 0) lmin = 0;
    int lmax = tp;       if (lmax > 1022) lmax = 1022;
    return (float)(lmax - lmin + 1);
}

__global__ void k_zero() {
    int i = blockIdx.x * 256 + threadIdx.x;
    if (i < 2*TPP*CC) g_acc[i] = 0.f;
    if (i < CC) g_colsum[i] = 0.f;
}

__global__ void k_transpose(const float* __restrict__ wi,
                            const float* __restrict__ wo,
                            const float* __restrict__ wp) {
    int idx = blockIdx.x * 256 + threadIdx.x;
    if (idx < E3*CC) {
        int e = idx >> 8, c = idx & 255;
        g_wti[c*E3 + e] = wi[idx];
    }
    if (idx < CC*CC) {
        int e = idx >> 8, c = idx & 255;
        g_wto[c*CC + e] = wo[idx];
        g_wtp[c*CC + e] = wp[idx];
    }
}

// ---------------- LayerNorm + z = LN(x) @ Win^T (bias hoisted) -----------
__global__ __launch_bounds__(256) void k_ln_z(const float* __restrict__ x,
                                              const float* __restrict__ lg,
                                              const float* __restrict__ lb) {
    __shared__ float Y[4][CC];
    __shared__ float sA[4][8], sB[4][8];
    int tid = threadIdx.x, warp = tid >> 5, lane = tid & 31;
    int row0 = blockIdx.x * 4;

    float gv = lg[tid], bv = lb[tid];
    float xv[4];
#pragma unroll
    for (int r = 0; r < 4; r++) {
        float v = x[(row0 + r)*CC + tid];
        xv[r] = v;
        float s = v, s2 = v*v;
#pragma unroll
        for (int o = 16; o; o >>= 1) {
            s  += __shfl_xor_sync(0xffffffffu, s, o);
            s2 += __shfl_xor_sync(0xffffffffu, s2, o);
        }
        if (lane == 0) { sA[r][warp] = s; sB[r][warp] = s2; }
    }
    __syncthreads();
#pragma unroll
    for (int r = 0; r < 4; r++) {
        float s = 0.f, s2 = 0.f;
#pragma unroll
        for (int w2 = 0; w2 < 8; w2++) { s += sA[r][w2]; s2 += sB[r][w2]; }
        float mu  = s * (1.f/CC);
        float var = s2 * (1.f/CC) - mu*mu;
        float rstd = rsqrtf(var + 1e-5f);
        Y[r][tid] = (xv[r] - mu) * rstd * gv + bv;
    }
    __syncthreads();

    float acc[4][3];
#pragma unroll
    for (int r = 0; r < 4; r++)
#pragma unroll
        for (int j = 0; j < 3; j++) acc[r][j] = 0.f;

    for (int c = 0; c < CC; c++) {
        float y4[4];
#pragma unroll
        for (int r = 0; r < 4; r++) y4[r] = Y[r][c];
#pragma unroll
        for (int j = 0; j < 3; j++) {
            float wv = g_wti[c*E3 + j*256 + tid];
#pragma unroll
            for (int r = 0; r < 4; r++) acc[r][j] += y4[r]*wv;
        }
    }
#pragma unroll
    for (int r = 0; r < 4; r++)
#pragma unroll
        for (int j = 0; j < 3; j++)
            g_z[(row0 + r)*E3 + j*256 + tid] = acc[r][j];
}

// ---------------- windowed attention v4 ----------------------------------
__global__ __launch_bounds__(ATHREADS, 2) void k_attn(const float* __restrict__ inb) {
    extern __shared__ unsigned char smraw[];
    __nv_bfloat16* Gm = (__nv_bfloat16*)smraw;          // [136][138] bf16; later P
    uint32_t* Zq = (uint32_t*)(smraw + OFF_ZQ);         // [136][34] bf16x2
    uint32_t* Zk = (uint32_t*)(smraw + OFF_ZK);         // [136][34] bf16x2
    float* Fs   = (float*)(smraw + OFF_F);
    float* Us   = Fs + F_US;
    float* Wvs  = Fs + F_WVS;
    float* invA = Fs + F_INVA;
    float* Hn   = Fs + F_HN;      // [130] (128 + 2 zero pad)
    float* bqS  = Fs + F_BQ;
    float* bkS  = Fs + F_BK;
    float* c0S  = Fs + F_C0;
    uint32_t* Hn2e = (uint32_t*)(Fs + F_HN2E);   // (Hn[2j],Hn[2j+1])
    uint32_t* Hn2o = (uint32_t*)(Fs + F_HN2O);   // (Hn[2j+1],Hn[2j+2])
    __nv_bfloat16* Wvb = (__nv_bfloat16*)(Fs + F_WVB); // bf16 copy of Wvs
    float* HnP  = Fs + F_HNP;     // [144] zero-padded Hn
    uint32_t* Zv = Zq;            // alias (Zq dead after G phase)

    int tid = threadIdx.x;
    int g = blockIdx.x, h = blockIdx.y, v = blockIdx.z;
    int l0 = g * WPB;

    if (tid < 130)
        Hn[tid] = (tid < 128)
            ? 0.5f*(1.f - cosf(6.283185307179586f*(float)tid/127.f)) : 0.f;
    if (tid >= 192 && tid < 256) bqS[tid-192] = inb[h*64 + (tid-192)];
    if (tid >= 256 && tid < 320) bkS[tid-256] = inb[CC + h*64 + (tid-256)];

    // load Zq / Zk (bf16 packed)
    for (int i = tid; i < RB*32; i += ATHREADS) {
        int r = i >> 5, jw = i & 31;
        int tp = l0 + r;
        float2 aq = make_float2(0.f, 0.f), ak = make_float2(0.f, 0.f);
        if (tp >= PADN && tp < PADN + TT) {
            int src = v ? ((tp - PADN - SHIFTN + TT) & (TT-1)) : (tp - PADN);
            const float* zp = &g_z[src*E3 + h*64 + 2*jw];
            aq = *(const float2*)zp;
            ak = *(const float2*)(zp + CC);
        }
        Zq[r*34 + jw] = f2b2(aq.x, aq.y);
        Zk[r*34 + jw] = f2b2(ak.x, ak.y);
    }
    __syncthreads();

    // ---- G (HFMA2, rows strided by 34 to stay conflict-free) ----
    for (int idx = tid; idx < 34*34; idx += ATHREADS) {
        int ta = idx / 34, tb = idx - ta*34;
        __nv_bfloat162 acc2[4][4];
        __nv_bfloat162 z2 = __float2bfloat162_rn(0.f);
#pragma unroll
        for (int i = 0; i < 4; i++)
#pragma unroll
            for (int i2 = 0; i2 < 4; i2++) acc2[i][i2] = z2;
        for (int jw = 0; jw < 32; jw += 2) {
            uint2 A[4], B[4];
#pragma unroll
            for (int i = 0; i < 4; i++) {
                A[i] = *(const uint2*)&Zq[(ta + 34*i)*34 + jw];
                B[i] = *(const uint2*)&Zk[(tb + 34*i)*34 + jw];
            }
#pragma unroll
            for (int i = 0; i < 4; i++)
#pragma unroll
                for (int i2 = 0; i2 < 4; i2++) {
                    acc2[i][i2] = __hfma2(u2b(A[i].x), u2b(B[i2].x), acc2[i][i2]);
                    acc2[i][i2] = __hfma2(u2b(A[i].y), u2b(B[i2].y), acc2[i][i2]);
                }
        }
#pragma unroll
        for (int i = 0; i < 4; i++)
#pragma unroll
            for (int i2 = 0; i2 < 4; i2++) {
                float gf = SCC*(__low2float(acc2[i][i2]) + __high2float(acc2[i][i2]));
                Gm[(ta + 34*i)*GST + tb + 34*i2] = __float2bfloat16_rn(gf);
            }
    }
    // u[a] = SCC * Zq[a].bk ; w[b] = SCC * bq.Zk[b] (+ bf16 copy Wvb)
    if (tid < 136) {
        float su = 0.f;
        for (int jw = 0; jw < 32; jw++) {
            float2 q2 = b2f(Zq[tid*34 + jw]);
            su += q2.x*bkS[2*jw] + q2.y*bkS[2*jw+1];
        }
        Us[tid] = SCC*su;
    } else if (tid < 272) {
        int r = tid - 136;
        float sw = 0.f;
        for (int jw = 0; jw < 32; jw++) {
            float2 k2 = b2f(Zk[r*34 + jw]);
            sw += k2.x*bqS[2*jw] + k2.y*bqS[2*jw+1];
        }
        float wv = SCC*sw;
        Wvs[r] = wv;
        Wvb[r] = __float2bfloat16_rn(wv);
    } else if (tid == 272) {
        float c0 = 0.f;
        for (int j = 0; j < 64; j++) c0 += bqS[j]*bkS[j];
        c0S[0] = SCC*c0;
    }
    // tables from Hn (Hn written pre-sync-1; read-only here)
    if (tid >= 288 && tid < 352) {
        int j = tid - 288;
        Hn2e[j] = f2b2(Hn[2*j], Hn[2*j+1]);
    } else if (tid >= 352 && tid < 416) {
        int j = tid - 352;
        Hn2o[j] = f2b2(Hn[2*j+1], Hn[2*j+2]);
    } else if (tid >= 416 && tid < 512) {
        int i0 = tid - 416;
        for (int i = i0; i < 144; i += 96)
            HnP[i] = (i >= 8 && i < 136) ? Hn[i-8] : 0.f;
    }
    __syncthreads();

    // ---- load Zv (overwrites Zq) + pass A: softmax denominators ----
    for (int i = tid; i < RB*32; i += ATHREADS) {
        int r = i >> 5, jw = i & 31;
        int tp = l0 + r;
        float2 av = make_float2(0.f, 0.f);
        if (tp >= PADN && tp < PADN + TT) {
            int src = v ? ((tp - PADN - SHIFTN + TT) & (TT-1)) : (tp - PADN);
            av = *(const float2*)&g_z[src*E3 + 2*CC + h*64 + 2*jw];
        }
        Zv[r*34 + jw] = f2b2(av.x, av.y);
    }
    float c0 = c0S[0];
    for (int rr = tid; rr < 1024; rr += ATHREADS) {
        int dl = rr >> 7, q = rr & 127;
        if (l0 + dl >= LW) continue;
        int a = dl + q;
        float hq = Hn[q];
        float base = fmaf(hq, Us[a], c0);
        __nv_bfloat162 hq2 = __float2bfloat162_rn(hq);
        __nv_bfloat162 base2 = __float2bfloat162_rn(base);
        int odd = dl & 1;
        int e0 = dl + odd;                         // first even offset
        const uint32_t* gp = (const uint32_t*)(Gm + a*GST + e0);
        const uint32_t* wp = (const uint32_t*)Wvb + (e0 >> 1);
        const uint32_t* hp = odd ? Hn2o : Hn2e;
        int npairs = 64 - odd;
        float sum = odd ? 2.f*exp2f(base) : 0.f;
#pragma unroll 4
        for (int j = 0; j < npairs; j++) {
            __nv_bfloat162 s2 = __hfma2(
                __hfma2(hq2, u2b(gp[j]), u2b(wp[j])), u2b(hp[j]), base2);
            float2 sf = __bfloat1622float2(s2);
            sum += exp2f(sf.x) + exp2f(sf.y);
        }
        invA[dl*128 + q] = 1.f/sum;
    }
    __syncthreads();

    // ---- pass B: P[a][b] gathered in place over G (predicate-free) ----
    for (int a = tid >> 2; a < 136; a += 128) {
        float gq[8], base[8], iv[8];
        float ua = Us[a];
#pragma unroll
        for (int dl = 0; dl < 8; dl++) {
            int qd = a - dl;
            bool va = (qd >= 0 && qd < 128);
            float hq = va ? Hn[qd] : 0.f;
            gq[dl] = hq;
            base[dl] = fmaf(hq, ua, c0);
            iv[dl] = (va && (l0 + dl) < LW) ? invA[dl*128 + qd] : 0.f;
        }
        int q4 = tid & 3;
        for (int jj = 0; jj < 34; jj++) {
            int b = q4 + 4*jj;
            float gval = b2f1(Gm[a*GST + b]);
            float wb = Wvs[b];
            const float* hP = &HnP[b + 8];
            float p = 0.f;
#pragma unroll
            for (int dl = 0; dl < 8; dl++) {
                float hk = hP[-dl];
                float s = fmaf(fmaf(gq[dl], gval, wb), hk, base[dl]);
                p = fmaf(hk*iv[dl], exp2f(s), p);
            }
            Gm[a*GST + b] = __float2bfloat16_rn(p);
        }
    }
    __syncthreads();

    // ---- PV (HFMA2 + f32 flush): acc[a][j] = sum_b P[a][b]*Zv[b][j] ----
    for (int idx = tid; idx < 68*8; idx += ATHREADS) {
        int ta = idx >> 3, tj = idx & 7;
        int a0 = ta*2, j0 = tj*8;
        float2 accf[2][4];
#pragma unroll
        for (int i = 0; i < 2; i++)
#pragma unroll
            for (int c = 0; c < 4; c++) accf[i][c] = make_float2(0.f, 0.f);
        __nv_bfloat162 z2 = __float2bfloat162_rn(0.f);
        for (int cb = 0; cb < 68; cb += 8) {
            int ce = (cb + 8 < 68) ? cb + 8 : 68;
            __nv_bfloat162 acc2[2][4];
#pragma unroll
            for (int i = 0; i < 2; i++)
#pragma unroll
                for (int c = 0; c < 4; c++) acc2[i][c] = z2;
            for (int bw = cb; bw < ce; bw++) {
                // uint2 loads only: odd-row word offsets are 2 mod 4, so
                // LDS.128 would be misaligned — LDS.64 is always safe here.
                const uint32_t* r0 = &Zv[(2*bw)*34 + (j0 >> 1)];
                const uint32_t* r1 = &Zv[(2*bw+1)*34 + (j0 >> 1)];
                uint2 V0a = *(const uint2*)r0;
                uint2 V0b = *(const uint2*)(r0 + 2);
                uint2 V1a = *(const uint2*)r1;
                uint2 V1b = *(const uint2*)(r1 + 2);
#pragma unroll
                for (int i = 0; i < 2; i++) {
                    __nv_bfloat162 pp = u2b(*(const uint32_t*)&Gm[(a0+i)*GST + 2*bw]);
                    __nv_bfloat162 pl = __low2bfloat162(pp);
                    __nv_bfloat162 ph = __high2bfloat162(pp);
                    acc2[i][0] = __hfma2(pl, u2b(V0a.x), acc2[i][0]);
                    acc2[i][1] = __hfma2(pl, u2b(V0a.y), acc2[i][1]);
                    acc2[i][2] = __hfma2(pl, u2b(V0b.x), acc2[i][2]);
                    acc2[i][3] = __hfma2(pl, u2b(V0b.y), acc2[i][3]);
                    acc2[i][0] = __hfma2(ph, u2b(V1a.x), acc2[i][0]);
                    acc2[i][1] = __hfma2(ph, u2b(V1a.y), acc2[i][1]);
                    acc2[i][2] = __hfma2(ph, u2b(V1b.x), acc2[i][2]);
                    acc2[i][3] = __hfma2(ph, u2b(V1b.y), acc2[i][3]);
                }
            }
#pragma unroll
            for (int i = 0; i < 2; i++)
#pragma unroll
                for (int c = 0; c < 4; c++) {
                    float2 f = __bfloat1622float2(acc2[i][c]);
                    accf[i][c].x += f.x;
                    accf[i][c].y += f.y;
                }
        }
#pragma unroll
        for (int i = 0; i < 2; i++) {
            int tp = l0 + a0 + i;
            if (tp < TPP) {
                float* dst = &g_acc[((size_t)v*TPP + tp)*CC + h*64 + j0];
#pragma unroll
                for (int c = 0; c < 4; c++) {
                    atomicAdd(&dst[2*c],   accf[i][c].x);
                    atomicAdd(&dst[2*c+1], accf[i][c].y);
                }
            }
        }
    }
}

// ---------------- finalize: combine variants + out-proj + proj -----------
__global__ __launch_bounds__(256) void k_finalize(const float* __restrict__ inb,
                                                  const float* __restrict__ ob,
                                                  const float* __restrict__ pb) {
    __shared__ float U[4][CC];
    __shared__ float Y2[4][CC];
    __shared__ float bb[4];
    int tid = threadIdx.x;
    int t0 = blockIdx.x * 4;
    float bvv = inb[2*CC + tid];

#pragma unroll
    for (int r = 0; r < 4; r++) {
        int t = t0 + r;
        float cm = cntf(t);
        float am = g_acc[(size_t)(t + PADN)*CC + tid];
        float pm = (am + cm*bvv) / (cm + 1e-6f);
        int tau = (t + SHIFTN) & (TT-1);
        float cs = cntf(tau);
        float as = g_acc[(size_t)TPP*CC + (size_t)(tau + PADN)*CC + tid];
        float ps = (as + cs*bvv) / (cs + 1e-6f);
        U[r][tid] = 0.5f*(pm + ps);
        if (tid == 0)
            bb[r] = 0.5f*(cm/(cm + 1e-6f) + cs/(cs + 1e-6f));
    }
    __syncthreads();

    float acc[4];
#pragma unroll
    for (int r = 0; r < 4; r++) acc[r] = 0.f;
    for (int c = 0; c < CC; c++) {
        float w = g_wto[c*CC + tid];
#pragma unroll
        for (int r = 0; r < 4; r++) acc[r] += U[r][c]*w;
    }
    float obv = ob[tid];
    __syncthreads();
#pragma unroll
    for (int r = 0; r < 4; r++) Y2[r][tid] = acc[r] + bb[r]*obv;
    __syncthreads();

#pragma unroll
    for (int r = 0; r < 4; r++) acc[r] = 0.f;
    for (int c = 0; c < CC; c++) {
        float w = g_wtp[c*CC + tid];
#pragma unroll
        for (int r = 0; r < 4; r++) acc[r] += Y2[r][c]*w;
    }
    float pbv = pb[tid];
    float colpart = 0.f;
#pragma unroll
    for (int r = 0; r < 4; r++) {
        float yp = acc[r] + pbv;
        g_y[(size_t)(t0 + r)*CC + tid] = yp;
        colpart += yp;
    }
    atomicAdd(&g_colsum[tid], colpart);
}

// ---------------- SE gate ----------------
__global__ __launch_bounds__(256) void k_se(const float* __restrict__ w1,
                                            const float* __restrict__ w2) {
    __shared__ float s[CC], s1[16];
    int tid = threadIdx.x;
    s[tid] = g_colsum[tid] * (1.f/(float)TT);
    __syncthreads();
    if (tid < 16) {
        float a = 0.f;
        for (int c = 0; c < CC; c++) a += s[c]*w1[tid*CC + c];
        s1[tid] = fmaxf(a, 0.f);
    }
    __syncthreads();
    float a = 0.f;
#pragma unroll
    for (int j = 0; j < 16; j++) a += s1[j]*w2[tid*16 + j];
    g_segate[tid] = 1.f/(1.f + __expf(-a));
}

// ---------------- residual + gate ----------------
__global__ void k_out(const float* __restrict__ x, float* __restrict__ out) {
    int i = blockIdx.x*256 + threadIdx.x;
    out[i] = x[i] + g_y[i]*g_segate[i & 255];
}

extern "C" void kernel_launch(void* const* d_in, const int* in_sizes, int n_in,
                              void* d_out, int out_size) {
    const float* x  = (const float*)d_in[0];
    const float* lg = (const float*)d_in[1];
    const float* lb = (const float*)d_in[2];
    const float* wi = (const float*)d_in[3];
    const float* ib = (const float*)d_in[4];
    const float* wo = (const float*)d_in[5];
    const float* ob = (const float*)d_in[6];
    const float* wp = (const float*)d_in[7];
    const float* pb = (const float*)d_in[8];
    const float* w1 = (const float*)d_in[9];
    const float* w2 = (const float*)d_in[10];
    float* out = (float*)d_out;

    cudaFuncSetAttribute(k_attn, cudaFuncAttributeMaxDynamicSharedMemorySize,
                         SMEM_BYTES);

    k_zero<<<2300, 256>>>();
    k_transpose<<<768, 256>>>(wi, wo, wp);
    k_ln_z<<<256, 256>>>(x, lg, lb);
    k_attn<<<dim3(128, 4, 2), ATHREADS, SMEM_BYTES>>>(ib);
    k_finalize<<<256, 256>>>(ib, ob, pb);
    k_se<<<1, 256>>>(w1, w2);
    k_out<<<1024, 256>>>(x, out);
}

// round 8
// speedup vs baseline: 2.0110x; 1.0683x over previous
#include <cuda_runtime.h>
#include <cuda_bf16.h>
#include <cstdint>
#include <stdint.h>

#define TT    1024
#define CC    256
#define E3    768
#define WINN  128
#define PADN  63
#define TPP   1150
#define LW    1023
#define SHIFTN 64
#define WPB   8
#define RB    136
#define GST   138
#define ZST   36
#define ATHREADS 512

// smem layout (bytes)
#define OFF_ZQ  37536          // Gm: 136*138 bf16 = 37536
#define OFF_ZK  57120          // Zq: 136*36*4 = 19584
#define OFF_F   76704          // Zk: 136*36*4 = 19584
#define SMEM_BYTES 84352

// Fs-region offsets (float slots)
#define F_US    0
#define F_WVS   136
#define F_INVA  272
#define F_HN    1296          // 130 used (+pad)
#define F_BQ    1428
#define F_BK    1492
#define F_C0    1556
#define F_HN2E  1560
#define F_HN2O  1624
#define F_WVB   1688          // 136 bf16 = 68 slots
#define F_HP2E  1756          // 73 u32
#define F_HP2O  1829          // 72 u32

// scale folded: 0.125 * log2(e)
#define SCC 0.18033688011112042f

__device__ float g_z[TT*E3];
__device__ float g_acc[2*TPP*CC];
__device__ float g_wti[CC*E3];
__device__ float g_wto[CC*CC];
__device__ float g_wtp[CC*CC];
__device__ float g_y[TT*CC];
__device__ float g_colsum[CC];
__device__ float g_segate[CC];

__device__ __forceinline__ float2 b2f(uint32_t u) {
    float2 r;
    r.x = __uint_as_float(u << 16);
    r.y = __uint_as_float(u & 0xffff0000u);
    return r;
}
__device__ __forceinline__ uint32_t f2b2(float a, float b) {
    __nv_bfloat162 t = __floats2bfloat162_rn(a, b);
    return *(uint32_t*)&t;
}
__device__ __forceinline__ float b2f1(__nv_bfloat16 h) {
    return __uint_as_float(((uint32_t)*(unsigned short*)&h) << 16);
}
__device__ __forceinline__ __nv_bfloat162 u2b(uint32_t u) {
    return *(__nv_bfloat162*)&u;
}

__device__ __forceinline__ float cntf(int t) {
    int tp = t + PADN;
    int lmin = tp - 127; if (lmin < 0) lmin = 0;
    int lmax = tp;       if (lmax > 1022) lmax = 1022;
    return (float)(lmax - lmin + 1);
}

// ---------------- init: zero accumulators + transpose weights ------------
__global__ void k_init(const float* __restrict__ wi,
                       const float* __restrict__ wo,
                       const float* __restrict__ wp) {
    int i = blockIdx.x * 256 + threadIdx.x;
    if (i < 2*TPP*CC) g_acc[i] = 0.f;
    if (i < CC) g_colsum[i] = 0.f;
    if (i < E3*CC) {
        int e = i >> 8, c = i & 255;
        g_wti[c*E3 + e] = wi[i];
    }
    if (i < CC*CC) {
        int e = i >> 8, c = i & 255;
        g_wto[c*CC + e] = wo[i];
        g_wtp[c*CC + e] = wp[i];
    }
}

// ---------------- LayerNorm + z = LN(x) @ Win^T (split-c, 512 thr) -------
__global__ __launch_bounds__(512) void k_ln_z(const float* __restrict__ x,
                                              const float* __restrict__ lg,
                                              const float* __restrict__ lb) {
    __shared__ float Y[4][CC];
    __shared__ float sA[4][8], sB[4][8];
    __shared__ float P[12][CC];
    int tid = threadIdx.x, half = tid >> 8, col = tid & 255;
    int warp = tid >> 5, lane = tid & 31;
    int w8 = warp & 7;
    int row0 = blockIdx.x * 4;

    float gv = lg[col], bv = lb[col];
    float xv[2];
#pragma unroll
    for (int r2 = 0; r2 < 2; r2++) {
        int r = 2*half + r2;
        float v = x[(row0 + r)*CC + col];
        xv[r2] = v;
        float s = v, s2 = v*v;
#pragma unroll
        for (int o = 16; o; o >>= 1) {
            s  += __shfl_xor_sync(0xffffffffu, s, o);
            s2 += __shfl_xor_sync(0xffffffffu, s2, o);
        }
        if (lane == 0) { sA[r][w8] = s; sB[r][w8] = s2; }
    }
    __syncthreads();
#pragma unroll
    for (int r2 = 0; r2 < 2; r2++) {
        int r = 2*half + r2;
        float s = 0.f, s2 = 0.f;
#pragma unroll
        for (int w2 = 0; w2 < 8; w2++) { s += sA[r][w2]; s2 += sB[r][w2]; }
        float mu  = s * (1.f/CC);
        float var = s2 * (1.f/CC) - mu*mu;
        float rstd = rsqrtf(var + 1e-5f);
        Y[r][col] = (xv[r2] - mu) * rstd * gv + bv;
    }
    __syncthreads();

    float acc[4][3];
#pragma unroll
    for (int r = 0; r < 4; r++)
#pragma unroll
        for (int j = 0; j < 3; j++) acc[r][j] = 0.f;

    int cbase = half * 128;
    for (int cc = 0; cc < 128; cc++) {
        int c = cbase + cc;
        float y4[4];
#pragma unroll
        for (int r = 0; r < 4; r++) y4[r] = Y[r][c];
#pragma unroll
        for (int j = 0; j < 3; j++) {
            float wv = g_wti[c*E3 + j*256 + col];
#pragma unroll
            for (int r = 0; r < 4; r++) acc[r][j] += y4[r]*wv;
        }
    }
    if (half) {
#pragma unroll
        for (int r = 0; r < 4; r++)
#pragma unroll
            for (int j = 0; j < 3; j++) P[r*3 + j][col] = acc[r][j];
    }
    __syncthreads();
    if (!half) {
#pragma unroll
        for (int r = 0; r < 4; r++)
#pragma unroll
            for (int j = 0; j < 3; j++)
                g_z[(row0 + r)*E3 + j*256 + col] = acc[r][j] + P[r*3 + j][col];
    }
}

// ---------------- windowed attention v5 ----------------------------------
__global__ __launch_bounds__(ATHREADS, 2) void k_attn(const float* __restrict__ inb) {
    extern __shared__ unsigned char smraw[];
    __nv_bfloat16* Gm = (__nv_bfloat16*)smraw;          // [136][138] bf16; later P
    uint32_t* Zq = (uint32_t*)(smraw + OFF_ZQ);         // [136][36] bf16x2
    uint32_t* Zk = (uint32_t*)(smraw + OFF_ZK);         // [136][36] bf16x2
    float* Fs   = (float*)(smraw + OFF_F);
    float* Us   = Fs + F_US;
    float* Wvs  = Fs + F_WVS;
    float* invA = Fs + F_INVA;
    float* Hn   = Fs + F_HN;      // [130] (128 + 2 zero pad)
    float* bqS  = Fs + F_BQ;
    float* bkS  = Fs + F_BK;
    float* c0S  = Fs + F_C0;
    uint32_t* Hn2e = (uint32_t*)(Fs + F_HN2E);   // (Hn[2j],Hn[2j+1])
    uint32_t* Hn2o = (uint32_t*)(Fs + F_HN2O);   // (Hn[2j+1],Hn[2j+2])
    __nv_bfloat16* Wvb = (__nv_bfloat16*)(Fs + F_WVB); // bf16 copy of Wvs
    uint32_t* HP2E = (uint32_t*)(Fs + F_HP2E);   // padded pairs, even start
    uint32_t* HP2O = (uint32_t*)(Fs + F_HP2O);   // padded pairs, odd start
    uint32_t* Zv = Zq;            // alias (Zq dead after G phase)

    int tid = threadIdx.x;
    int g = blockIdx.x, h = blockIdx.y, v = blockIdx.z;
    int l0 = g * WPB;

    if (tid < 130)
        Hn[tid] = (tid < 128)
            ? 0.5f*(1.f - cosf(6.283185307179586f*(float)tid/127.f)) : 0.f;
    if (tid >= 192 && tid < 256) bqS[tid-192] = inb[h*64 + (tid-192)];
    if (tid >= 256 && tid < 320) bkS[tid-256] = inb[CC + h*64 + (tid-256)];

    // load Zq / Zk (bf16 packed, row stride 36 words -> all rows 16B aligned)
    for (int i = tid; i < RB*32; i += ATHREADS) {
        int r = i >> 5, jw = i & 31;
        int tp = l0 + r;
        float2 aq = make_float2(0.f, 0.f), ak = make_float2(0.f, 0.f);
        if (tp >= PADN && tp < PADN + TT) {
            int src = v ? ((tp - PADN - SHIFTN + TT) & (TT-1)) : (tp - PADN);
            const float* zp = &g_z[src*E3 + h*64 + 2*jw];
            aq = *(const float2*)zp;
            ak = *(const float2*)(zp + CC);
        }
        Zq[r*ZST + jw] = f2b2(aq.x, aq.y);
        Zk[r*ZST + jw] = f2b2(ak.x, ak.y);
    }
    __syncthreads();

    // ---- G (HFMA2, LDS.128, rows strided by 34 -> conflict-free) ----
    for (int idx = tid; idx < 34*34; idx += ATHREADS) {
        int ta = idx / 34, tb = idx - ta*34;
        __nv_bfloat162 acc2[4][4];
        __nv_bfloat162 z2 = __float2bfloat162_rn(0.f);
#pragma unroll
        for (int i = 0; i < 4; i++)
#pragma unroll
            for (int i2 = 0; i2 < 4; i2++) acc2[i][i2] = z2;
        for (int jw = 0; jw < 32; jw += 4) {
            uint4 A[4], B[4];
#pragma unroll
            for (int i = 0; i < 4; i++) {
                A[i] = *(const uint4*)&Zq[(ta + 34*i)*ZST + jw];
                B[i] = *(const uint4*)&Zk[(tb + 34*i)*ZST + jw];
            }
#pragma unroll
            for (int i = 0; i < 4; i++)
#pragma unroll
                for (int i2 = 0; i2 < 4; i2++) {
                    acc2[i][i2] = __hfma2(u2b(A[i].x), u2b(B[i2].x), acc2[i][i2]);
                    acc2[i][i2] = __hfma2(u2b(A[i].y), u2b(B[i2].y), acc2[i][i2]);
                    acc2[i][i2] = __hfma2(u2b(A[i].z), u2b(B[i2].z), acc2[i][i2]);
                    acc2[i][i2] = __hfma2(u2b(A[i].w), u2b(B[i2].w), acc2[i][i2]);
                }
        }
#pragma unroll
        for (int i = 0; i < 4; i++)
#pragma unroll
            for (int i2 = 0; i2 < 4; i2++) {
                float gf = SCC*(__low2float(acc2[i][i2]) + __high2float(acc2[i][i2]));
                Gm[(ta + 34*i)*GST + tb + 34*i2] = __float2bfloat16_rn(gf);
            }
    }
    // u[a] = SCC * Zq[a].bk ; w[b] = SCC * bq.Zk[b] (+ bf16 copy Wvb)
#define HPF(i) (((i) >= 8 && (i) < 136) ? Hn[(i)-8] : 0.f)
    if (tid < 136) {
        float su = 0.f;
        for (int jw = 0; jw < 32; jw++) {
            float2 q2 = b2f(Zq[tid*ZST + jw]);
            su += q2.x*bkS[2*jw] + q2.y*bkS[2*jw+1];
        }
        Us[tid] = SCC*su;
    } else if (tid < 272) {
        int r = tid - 136;
        float sw = 0.f;
        for (int jw = 0; jw < 32; jw++) {
            float2 k2 = b2f(Zk[r*ZST + jw]);
            sw += k2.x*bqS[2*jw] + k2.y*bqS[2*jw+1];
        }
        float wv = SCC*sw;
        Wvs[r] = wv;
        Wvb[r] = __float2bfloat16_rn(wv);
    } else if (tid == 272) {
        float c0 = 0.f;
        for (int j = 0; j < 64; j++) c0 += bqS[j]*bkS[j];
        c0S[0] = SCC*c0;
    } else if (tid >= 288 && tid < 352) {
        int j = tid - 288;
        Hn2e[j] = f2b2(Hn[2*j], Hn[2*j+1]);
    } else if (tid >= 352 && tid < 416) {
        int j = tid - 352;
        Hn2o[j] = f2b2(Hn[2*j+1], Hn[2*j+2]);
    } else if (tid >= 416) {
        for (int j = tid - 416; j < 73; j += 96)
            HP2E[j] = f2b2(HPF(2*j), HPF(2*j+1));
        for (int j = tid - 416; j < 72; j += 96)
            HP2O[j] = f2b2(HPF(2*j+1), HPF(2*j+2));
    }
    __syncthreads();

    // ---- load Zv (overwrites Zq) + pass A: softmax denominators ----
    for (int i = tid; i < RB*32; i += ATHREADS) {
        int r = i >> 5, jw = i & 31;
        int tp = l0 + r;
        float2 av = make_float2(0.f, 0.f);
        if (tp >= PADN && tp < PADN + TT) {
            int src = v ? ((tp - PADN - SHIFTN + TT) & (TT-1)) : (tp - PADN);
            av = *(const float2*)&g_z[src*E3 + 2*CC + h*64 + 2*jw];
        }
        Zv[r*ZST + jw] = f2b2(av.x, av.y);
    }
    float c0 = c0S[0];
    for (int rr = tid; rr < 1024; rr += ATHREADS) {
        int dl = rr >> 7, q = rr & 127;
        if (l0 + dl >= LW) continue;
        int a = dl + q;
        float hq = Hn[q];
        float base = fmaf(hq, Us[a], c0);
        __nv_bfloat162 hq2 = __float2bfloat162_rn(hq);
        __nv_bfloat162 base2 = __float2bfloat162_rn(base);
        int odd = dl & 1;
        int e0 = dl + odd;                         // first even offset
        const uint32_t* gp = (const uint32_t*)(Gm + a*GST + e0);
        const uint32_t* wp = (const uint32_t*)Wvb + (e0 >> 1);
        const uint32_t* hp = odd ? Hn2o : Hn2e;
        int npairs = 64 - odd;
        float sum = odd ? 2.f*exp2f(base) : 0.f;
#pragma unroll 4
        for (int j = 0; j < npairs; j++) {
            __nv_bfloat162 s2 = __hfma2(
                __hfma2(hq2, u2b(gp[j]), u2b(wp[j])), u2b(hp[j]), base2);
            float2 sf = __bfloat1622float2(s2);
            sum += exp2f(sf.x) + exp2f(sf.y);
        }
        invA[dl*128 + q] = 1.f/sum;
    }
    __syncthreads();

    // ---- pass B: P[a][b] in place over G, 2-wide bf16x2 ----
    for (int a = tid >> 2; a < 136; a += 128) {
        uint32_t gq2[8], base2[8];
        float iv[8];
        float ua = Us[a];
#pragma unroll
        for (int dl = 0; dl < 8; dl++) {
            int qd = a - dl;
            bool va = (qd >= 0 && qd < 128);
            float hq = va ? Hn[qd] : 0.f;
            float bs = fmaf(hq, ua, c0);
            gq2[dl] = f2b2(hq, hq);
            base2[dl] = f2b2(bs, bs);
            iv[dl] = (va && (l0 + dl) < LW) ? invA[dl*128 + qd] : 0.f;
        }
        int q4 = tid & 3;
        for (int jj = 0; jj < 17; jj++) {
            int b2 = 2*q4 + 8*jj;
            uint32_t gval2 = *(const uint32_t*)&Gm[a*GST + b2];
            uint32_t wb2 = ((const uint32_t*)Wvb)[b2 >> 1];
            float p0 = 0.f, p1 = 0.f;
#pragma unroll
            for (int dl = 0; dl < 8; dl++) {
                uint32_t hk2u = (dl & 1)
                    ? HP2O[(b2 - dl + 7) >> 1]
                    : HP2E[(b2 - dl + 8) >> 1];
                __nv_bfloat162 s2 = __hfma2(
                    __hfma2(u2b(gq2[dl]), u2b(gval2), u2b(wb2)),
                    u2b(hk2u), u2b(base2[dl]));
                float2 sf = __bfloat1622float2(s2);
                float2 hk = b2f(hk2u);
                p0 = fmaf(hk.x*iv[dl], exp2f(sf.x), p0);
                p1 = fmaf(hk.y*iv[dl], exp2f(sf.y), p1);
            }
            *(uint32_t*)&Gm[a*GST + b2] = f2b2(p0, p1);
        }
    }
    __syncthreads();

    // ---- PV (HFMA2 + f32 flush, LDS.128 V loads) ----
    for (int idx = tid; idx < 68*8; idx += ATHREADS) {
        int ta = idx >> 3, tj = idx & 7;
        int a0 = ta*2, j0 = tj*8;
        float2 accf[2][4];
#pragma unroll
        for (int i = 0; i < 2; i++)
#pragma unroll
            for (int c = 0; c < 4; c++) accf[i][c] = make_float2(0.f, 0.f);
        __nv_bfloat162 z2 = __float2bfloat162_rn(0.f);
        for (int cb = 0; cb < 68; cb += 8) {
            int ce = (cb + 8 < 68) ? cb + 8 : 68;
            __nv_bfloat162 acc2[2][4];
#pragma unroll
            for (int i = 0; i < 2; i++)
#pragma unroll
                for (int c = 0; c < 4; c++) acc2[i][c] = z2;
            for (int bw = cb; bw < ce; bw++) {
                uint4 V0 = *(const uint4*)&Zv[(2*bw)*ZST + (j0 >> 1)];
                uint4 V1 = *(const uint4*)&Zv[(2*bw+1)*ZST + (j0 >> 1)];
#pragma unroll
                for (int i = 0; i < 2; i++) {
                    __nv_bfloat162 pp = u2b(*(const uint32_t*)&Gm[(a0+i)*GST + 2*bw]);
                    __nv_bfloat162 pl = __low2bfloat162(pp);
                    __nv_bfloat162 ph = __high2bfloat162(pp);
                    acc2[i][0] = __hfma2(pl, u2b(V0.x), acc2[i][0]);
                    acc2[i][1] = __hfma2(pl, u2b(V0.y), acc2[i][1]);
                    acc2[i][2] = __hfma2(pl, u2b(V0.z), acc2[i][2]);
                    acc2[i][3] = __hfma2(pl, u2b(V0.w), acc2[i][3]);
                    acc2[i][0] = __hfma2(ph, u2b(V1.x), acc2[i][0]);
                    acc2[i][1] = __hfma2(ph, u2b(V1.y), acc2[i][1]);
                    acc2[i][2] = __hfma2(ph, u2b(V1.z), acc2[i][2]);
                    acc2[i][3] = __hfma2(ph, u2b(V1.w), acc2[i][3]);
                }
            }
#pragma unroll
            for (int i = 0; i < 2; i++)
#pragma unroll
                for (int c = 0; c < 4; c++) {
                    float2 f = __bfloat1622float2(acc2[i][c]);
                    accf[i][c].x += f.x;
                    accf[i][c].y += f.y;
                }
        }
#pragma unroll
        for (int i = 0; i < 2; i++) {
            int tp = l0 + a0 + i;
            if (tp < TPP) {
                float* dst = &g_acc[((size_t)v*TPP + tp)*CC + h*64 + j0];
#pragma unroll
                for (int c = 0; c < 4; c++) {
                    atomicAdd(&dst[2*c],   accf[i][c].x);
                    atomicAdd(&dst[2*c+1], accf[i][c].y);
                }
            }
        }
    }
}

// ---------------- finalize (split-c, 512 thr) ----------------------------
__global__ __launch_bounds__(512) void k_finalize(const float* __restrict__ inb,
                                                  const float* __restrict__ ob,
                                                  const float* __restrict__ pb) {
    __shared__ float U[4][CC];
    __shared__ float Y2[4][CC];
    __shared__ float P[4][CC];
    __shared__ float bb[4];
    int tid = threadIdx.x, half = tid >> 8, col = tid & 255;
    int t0 = blockIdx.x * 4;

    for (int idx = tid; idx < 4*CC; idx += 512) {
        int r = idx >> 8, c = idx & 255;
        float bvv = inb[2*CC + c];
        int t = t0 + r;
        float cm = cntf(t);
        float am = g_acc[(size_t)(t + PADN)*CC + c];
        float pm = (am + cm*bvv) / (cm + 1e-6f);
        int tau = (t + SHIFTN) & (TT-1);
        float cs = cntf(tau);
        float as = g_acc[(size_t)TPP*CC + (size_t)(tau + PADN)*CC + c];
        float ps = (as + cs*bvv) / (cs + 1e-6f);
        U[r][c] = 0.5f*(pm + ps);
    }
    if (tid < 4) {
        int t = t0 + tid;
        float cm = cntf(t);
        float cs = cntf((t + SHIFTN) & (TT-1));
        bb[tid] = 0.5f*(cm/(cm + 1e-6f) + cs/(cs + 1e-6f));
    }
    __syncthreads();

    float acc[4];
    int cbase = half * 128;
#pragma unroll
    for (int r = 0; r < 4; r++) acc[r] = 0.f;
    for (int cc = 0; cc < 128; cc++) {
        int c = cbase + cc;
        float w = g_wto[c*CC + col];
#pragma unroll
        for (int r = 0; r < 4; r++) acc[r] += U[r][c]*w;
    }
    if (half) {
#pragma unroll
        for (int r = 0; r < 4; r++) P[r][col] = acc[r];
    }
    __syncthreads();
    if (!half) {
        float obv = ob[col];
#pragma unroll
        for (int r = 0; r < 4; r++)
            Y2[r][col] = acc[r] + P[r][col] + bb[r]*obv;
    }
    __syncthreads();

#pragma unroll
    for (int r = 0; r < 4; r++) acc[r] = 0.f;
    for (int cc = 0; cc < 128; cc++) {
        int c = cbase + cc;
        float w = g_wtp[c*CC + col];
#pragma unroll
        for (int r = 0; r < 4; r++) acc[r] += Y2[r][c]*w;
    }
    if (half) {
#pragma unroll
        for (int r = 0; r < 4; r++) P[r][col] = acc[r];
    }
    __syncthreads();
    if (!half) {
        float pbv = pb[col];
        float colpart = 0.f;
#pragma unroll
        for (int r = 0; r < 4; r++) {
            float yp = acc[r] + P[r][col] + pbv;
            g_y[(size_t)(t0 + r)*CC + col] = yp;
            colpart += yp;
        }
        atomicAdd(&g_colsum[col], colpart);
    }
}

// ---------------- SE gate ----------------
__global__ __launch_bounds__(256) void k_se(const float* __restrict__ w1,
                                            const float* __restrict__ w2) {
    __shared__ float s[CC], s1[16];
    int tid = threadIdx.x;
    s[tid] = g_colsum[tid] * (1.f/(float)TT);
    __syncthreads();
    if (tid < 16) {
        float a = 0.f;
        for (int c = 0; c < CC; c++) a += s[c]*w1[tid*CC + c];
        s1[tid] = fmaxf(a, 0.f);
    }
    __syncthreads();
    float a = 0.f;
#pragma unroll
    for (int j = 0; j < 16; j++) a += s1[j]*w2[tid*16 + j];
    g_segate[tid] = 1.f/(1.f + __expf(-a));
}

// ---------------- residual + gate ----------------
__global__ void k_out(const float* __restrict__ x, float* __restrict__ out) {
    int i = blockIdx.x*256 + threadIdx.x;
    out[i] = x[i] + g_y[i]*g_segate[i & 255];
}

extern "C" void kernel_launch(void* const* d_in, const int* in_sizes, int n_in,
                              void* d_out, int out_size) {
    const float* x  = (const float*)d_in[0];
    const float* lg = (const float*)d_in[1];
    const float* lb = (const float*)d_in[2];
    const float* wi = (const float*)d_in[3];
    const float* ib = (const float*)d_in[4];
    const float* wo = (const float*)d_in[5];
    const float* ob = (const float*)d_in[6];
    const float* wp = (const float*)d_in[7];
    const float* pb = (const float*)d_in[8];
    const float* w1 = (const float*)d_in[9];
    const float* w2 = (const float*)d_in[10];
    float* out = (float*)d_out;

    cudaFuncSetAttribute(k_attn, cudaFuncAttributeMaxDynamicSharedMemorySize,
                         SMEM_BYTES);

    k_init<<<2300, 256>>>(wi, wo, wp);
    k_ln_z<<<256, 512>>>(x, lg, lb);
    k_attn<<<dim3(128, 4, 2), ATHREADS, SMEM_BYTES>>>(ib);
    k_finalize<<<256, 512>>>(ib, ob, pb);
    k_se<<<1, 256>>>(w1, w2);
    k_out<<<1024, 256>>>(x, out);
}

// round 9
// speedup vs baseline: 2.6660x; 1.3257x over previous
#include <cuda_runtime.h>
#include <cuda_bf16.h>
#include <cstdint>
#include <stdint.h>

#define TT    1024
#define CC    256
#define E3    768
#define WINN  128
#define PADN  63
#define TPP   1150
#define LW    1023
#define SHIFTN 64
#define WPB   8
#define RB    136
#define GST   138
#define ZST   36
#define ATHREADS 512

// smem layout (bytes)
#define OFF_ZQ  37536          // Gm: 136*138 bf16 = 37536
#define OFF_ZK  57120          // Zq: 136*36*4 = 19584
#define OFF_F   76704          // Zk: 136*36*4 = 19584
#define SMEM_BYTES 84352

// Fs-region offsets (float slots)
#define F_US    0
#define F_WVS   136
#define F_INVA  272
#define F_HN    1296          // 130 used (+pad)
#define F_BQ    1428
#define F_BK    1492
#define F_C0    1556
#define F_HN2E  1560
#define F_HN2O  1624
#define F_WVB   1688          // 136 bf16 = 68 slots
#define F_HP2E  1756          // 73 u32
#define F_HP2O  1829          // 72 u32

// scale folded: 0.125 * log2(e)
#define SCC 0.18033688011112042f

__device__ float g_z[TT*E3];
__device__ float g_acc[2*TPP*CC];
__device__ float g_wti[CC*E3];
__device__ float g_wto[CC*CC];
__device__ float g_wtp[CC*CC];
__device__ float g_y[TT*CC];
__device__ float g_colsum[CC];
__device__ float g_segate[CC];

__device__ __forceinline__ float2 b2f(uint32_t u) {
    float2 r;
    r.x = __uint_as_float(u << 16);
    r.y = __uint_as_float(u & 0xffff0000u);
    return r;
}
__device__ __forceinline__ uint32_t f2b2(float a, float b) {
    __nv_bfloat162 t = __floats2bfloat162_rn(a, b);
    return *(uint32_t*)&t;
}
__device__ __forceinline__ float b2f1(__nv_bfloat16 h) {
    return __uint_as_float(((uint32_t)*(unsigned short*)&h) << 16);
}
__device__ __forceinline__ __nv_bfloat162 u2b(uint32_t u) {
    return *(__nv_bfloat162*)&u;
}

__device__ __forceinline__ float cntf(int t) {
    int tp = t + PADN;
    int lmin = tp - 127; if (lmin < 0) lmin = 0;
    int lmax = tp;       if (lmax > 1022) lmax = 1022;
    return (float)(lmax - lmin + 1);
}

// ---------------- init: zero accumulators + transpose weights ------------
__global__ void k_init(const float* __restrict__ wi,
                       const float* __restrict__ wo,
                       const float* __restrict__ wp) {
    int i = blockIdx.x * 256 + threadIdx.x;
    if (i < 2*TPP*CC) g_acc[i] = 0.f;
    if (i < CC) g_colsum[i] = 0.f;
    if (i < E3*CC) {
        int e = i >> 8, c = i & 255;
        g_wti[c*E3 + e] = wi[i];
    }
    if (i < CC*CC) {
        int e = i >> 8, c = i & 255;
        g_wto[c*CC + e] = wo[i];
        g_wtp[c*CC + e] = wp[i];
    }
}

// ---------------- LayerNorm + z = LN(x) @ Win^T (split-c, 512 thr) -------
__global__ __launch_bounds__(512) void k_ln_z(const float* __restrict__ x,
                                              const float* __restrict__ lg,
                                              const float* __restrict__ lb) {
    __shared__ float Y[4][CC];
    __shared__ float sA[4][8], sB[4][8];
    __shared__ float P[12][CC];
    int tid = threadIdx.x, half = tid >> 8, col = tid & 255;
    int warp = tid >> 5, lane = tid & 31;
    int w8 = warp & 7;
    int row0 = blockIdx.x * 4;

    float gv = lg[col], bv = lb[col];
    float xv[2];
#pragma unroll
    for (int r2 = 0; r2 < 2; r2++) {
        int r = 2*half + r2;
        float v = x[(row0 + r)*CC + col];
        xv[r2] = v;
        float s = v, s2 = v*v;
#pragma unroll
        for (int o = 16; o; o >>= 1) {
            s  += __shfl_xor_sync(0xffffffffu, s, o);
            s2 += __shfl_xor_sync(0xffffffffu, s2, o);
        }
        if (lane == 0) { sA[r][w8] = s; sB[r][w8] = s2; }
    }
    __syncthreads();
#pragma unroll
    for (int r2 = 0; r2 < 2; r2++) {
        int r = 2*half + r2;
        float s = 0.f, s2 = 0.f;
#pragma unroll
        for (int w2 = 0; w2 < 8; w2++) { s += sA[r][w2]; s2 += sB[r][w2]; }
        float mu  = s * (1.f/CC);
        float var = s2 * (1.f/CC) - mu*mu;
        float rstd = rsqrtf(var + 1e-5f);
        Y[r][col] = (xv[r2] - mu) * rstd * gv + bv;
    }
    __syncthreads();

    float acc[4][3];
#pragma unroll
    for (int r = 0; r < 4; r++)
#pragma unroll
        for (int j = 0; j < 3; j++) acc[r][j] = 0.f;

    int cbase = half * 128;
#pragma unroll 4
    for (int cc = 0; cc < 128; cc++) {
        int c = cbase + cc;
        float y4[4];
#pragma unroll
        for (int r = 0; r < 4; r++) y4[r] = Y[r][c];
#pragma unroll
        for (int j = 0; j < 3; j++) {
            float wv = g_wti[c*E3 + j*256 + col];
#pragma unroll
            for (int r = 0; r < 4; r++) acc[r][j] += y4[r]*wv;
        }
    }
    if (half) {
#pragma unroll
        for (int r = 0; r < 4; r++)
#pragma unroll
            for (int j = 0; j < 3; j++) P[r*3 + j][col] = acc[r][j];
    }
    __syncthreads();
    if (!half) {
#pragma unroll
        for (int r = 0; r < 4; r++)
#pragma unroll
            for (int j = 0; j < 3; j++)
                g_z[(row0 + r)*E3 + j*256 + col] = acc[r][j] + P[r*3 + j][col];
    }
}

// ---------------- windowed attention v6: shift-dedup ----------------------
// v1 group g duplicates v0 group g-8 whenever 16 <= g < 119 (exact identity:
// same sources, same zero-masks, no wrap). Those blocks are not launched;
// instead v0 blocks with 8 <= g < 111 dual-scatter into acc[1] at tp+64.
__global__ __launch_bounds__(ATHREADS, 2) void k_attn(const float* __restrict__ inb) {
    extern __shared__ unsigned char smraw[];
    __nv_bfloat16* Gm = (__nv_bfloat16*)smraw;          // [136][138] bf16; later P
    uint32_t* Zq = (uint32_t*)(smraw + OFF_ZQ);         // [136][36] bf16x2
    uint32_t* Zk = (uint32_t*)(smraw + OFF_ZK);         // [136][36] bf16x2
    float* Fs   = (float*)(smraw + OFF_F);
    float* Us   = Fs + F_US;
    float* Wvs  = Fs + F_WVS;
    float* invA = Fs + F_INVA;
    float* Hn   = Fs + F_HN;      // [130] (128 + 2 zero pad)
    float* bqS  = Fs + F_BQ;
    float* bkS  = Fs + F_BK;
    float* c0S  = Fs + F_C0;
    uint32_t* Hn2e = (uint32_t*)(Fs + F_HN2E);   // (Hn[2j],Hn[2j+1])
    uint32_t* Hn2o = (uint32_t*)(Fs + F_HN2O);   // (Hn[2j+1],Hn[2j+2])
    __nv_bfloat16* Wvb = (__nv_bfloat16*)(Fs + F_WVB); // bf16 copy of Wvs
    uint32_t* HP2E = (uint32_t*)(Fs + F_HP2E);   // padded pairs, even start
    uint32_t* HP2O = (uint32_t*)(Fs + F_HP2O);   // padded pairs, odd start
    uint32_t* Zv = Zq;            // alias (Zq dead after G phase)

    int tid = threadIdx.x;
    int bx = blockIdx.x, h = blockIdx.y;
    int v, g;
    if (bx < 128) { v = 0; g = bx; }
    else { int i = bx - 128; v = 1; g = (i < 16) ? i : i + 103; }
    bool dual = (v == 0) && (g >= 8) && (g < 111);
    int l0 = g * WPB;

    if (tid < 130)
        Hn[tid] = (tid < 128)
            ? 0.5f*(1.f - cosf(6.283185307179586f*(float)tid/127.f)) : 0.f;
    if (tid >= 192 && tid < 256) bqS[tid-192] = inb[h*64 + (tid-192)];
    if (tid >= 256 && tid < 320) bkS[tid-256] = inb[CC + h*64 + (tid-256)];

    // load Zq / Zk (bf16 packed, row stride 36 words -> all rows 16B aligned)
    for (int i = tid; i < RB*32; i += ATHREADS) {
        int r = i >> 5, jw = i & 31;
        int tp = l0 + r;
        float2 aq = make_float2(0.f, 0.f), ak = make_float2(0.f, 0.f);
        if (tp >= PADN && tp < PADN + TT) {
            int src = v ? ((tp - PADN - SHIFTN + TT) & (TT-1)) : (tp - PADN);
            const float* zp = &g_z[src*E3 + h*64 + 2*jw];
            aq = *(const float2*)zp;
            ak = *(const float2*)(zp + CC);
        }
        Zq[r*ZST + jw] = f2b2(aq.x, aq.y);
        Zk[r*ZST + jw] = f2b2(ak.x, ak.y);
    }
    __syncthreads();

    // ---- G (HFMA2, LDS.128, rows strided by 34 -> conflict-free) ----
    for (int idx = tid; idx < 34*34; idx += ATHREADS) {
        int ta = idx / 34, tb = idx - ta*34;
        __nv_bfloat162 acc2[4][4];
        __nv_bfloat162 z2 = __float2bfloat162_rn(0.f);
#pragma unroll
        for (int i = 0; i < 4; i++)
#pragma unroll
            for (int i2 = 0; i2 < 4; i2++) acc2[i][i2] = z2;
        for (int jw = 0; jw < 32; jw += 4) {
            uint4 A[4], B[4];
#pragma unroll
            for (int i = 0; i < 4; i++) {
                A[i] = *(const uint4*)&Zq[(ta + 34*i)*ZST + jw];
                B[i] = *(const uint4*)&Zk[(tb + 34*i)*ZST + jw];
            }
#pragma unroll
            for (int i = 0; i < 4; i++)
#pragma unroll
                for (int i2 = 0; i2 < 4; i2++) {
                    acc2[i][i2] = __hfma2(u2b(A[i].x), u2b(B[i2].x), acc2[i][i2]);
                    acc2[i][i2] = __hfma2(u2b(A[i].y), u2b(B[i2].y), acc2[i][i2]);
                    acc2[i][i2] = __hfma2(u2b(A[i].z), u2b(B[i2].z), acc2[i][i2]);
                    acc2[i][i2] = __hfma2(u2b(A[i].w), u2b(B[i2].w), acc2[i][i2]);
                }
        }
#pragma unroll
        for (int i = 0; i < 4; i++)
#pragma unroll
            for (int i2 = 0; i2 < 4; i2++) {
                float gf = SCC*(__low2float(acc2[i][i2]) + __high2float(acc2[i][i2]));
                Gm[(ta + 34*i)*GST + tb + 34*i2] = __float2bfloat16_rn(gf);
            }
    }
    // u[a] = SCC * Zq[a].bk ; w[b] = SCC * bq.Zk[b] (+ bf16 copy Wvb)
#define HPF(i) (((i) >= 8 && (i) < 136) ? Hn[(i)-8] : 0.f)
    if (tid < 136) {
        float su = 0.f;
        for (int jw = 0; jw < 32; jw++) {
            float2 q2 = b2f(Zq[tid*ZST + jw]);
            su += q2.x*bkS[2*jw] + q2.y*bkS[2*jw+1];
        }
        Us[tid] = SCC*su;
    } else if (tid < 272) {
        int r = tid - 136;
        float sw = 0.f;
        for (int jw = 0; jw < 32; jw++) {
            float2 k2 = b2f(Zk[r*ZST + jw]);
            sw += k2.x*bqS[2*jw] + k2.y*bqS[2*jw+1];
        }
        float wv = SCC*sw;
        Wvs[r] = wv;
        Wvb[r] = __float2bfloat16_rn(wv);
    } else if (tid == 272) {
        float c0 = 0.f;
        for (int j = 0; j < 64; j++) c0 += bqS[j]*bkS[j];
        c0S[0] = SCC*c0;
    } else if (tid >= 288 && tid < 352) {
        int j = tid - 288;
        Hn2e[j] = f2b2(Hn[2*j], Hn[2*j+1]);
    } else if (tid >= 352 && tid < 416) {
        int j = tid - 352;
        Hn2o[j] = f2b2(Hn[2*j+1], Hn[2*j+2]);
    } else if (tid >= 416) {
        for (int j = tid - 416; j < 73; j += 96)
            HP2E[j] = f2b2(HPF(2*j), HPF(2*j+1));
        for (int j = tid - 416; j < 72; j += 96)
            HP2O[j] = f2b2(HPF(2*j+1), HPF(2*j+2));
    }
    __syncthreads();

    // ---- load Zv (overwrites Zq) + pass A: softmax denominators ----
    for (int i = tid; i < RB*32; i += ATHREADS) {
        int r = i >> 5, jw = i & 31;
        int tp = l0 + r;
        float2 av = make_float2(0.f, 0.f);
        if (tp >= PADN && tp < PADN + TT) {
            int src = v ? ((tp - PADN - SHIFTN + TT) & (TT-1)) : (tp - PADN);
            av = *(const float2*)&g_z[src*E3 + 2*CC + h*64 + 2*jw];
        }
        Zv[r*ZST + jw] = f2b2(av.x, av.y);
    }
    float c0 = c0S[0];
    for (int rr = tid; rr < 1024; rr += ATHREADS) {
        int dl = rr >> 7, q = rr & 127;
        if (l0 + dl >= LW) continue;
        int a = dl + q;
        float hq = Hn[q];
        float base = fmaf(hq, Us[a], c0);
        __nv_bfloat162 hq2 = __float2bfloat162_rn(hq);
        __nv_bfloat162 base2 = __float2bfloat162_rn(base);
        int odd = dl & 1;
        int e0 = dl + odd;                         // first even offset
        const uint32_t* gp = (const uint32_t*)(Gm + a*GST + e0);
        const uint32_t* wp = (const uint32_t*)Wvb + (e0 >> 1);
        const uint32_t* hp = odd ? Hn2o : Hn2e;
        int npairs = 64 - odd;
        float sum = odd ? 2.f*exp2f(base) : 0.f;
#pragma unroll 4
        for (int j = 0; j < npairs; j++) {
            __nv_bfloat162 s2 = __hfma2(
                __hfma2(hq2, u2b(gp[j]), u2b(wp[j])), u2b(hp[j]), base2);
            float2 sf = __bfloat1622float2(s2);
            sum += exp2f(sf.x) + exp2f(sf.y);
        }
        invA[dl*128 + q] = 1.f/sum;
    }
    __syncthreads();

    // ---- pass B: P[a][b] in place over G, 2-wide bf16x2 ----
    for (int a = tid >> 2; a < 136; a += 128) {
        uint32_t gq2[8], base2[8];
        float iv[8];
        float ua = Us[a];
#pragma unroll
        for (int dl = 0; dl < 8; dl++) {
            int qd = a - dl;
            bool va = (qd >= 0 && qd < 128);
            float hq = va ? Hn[qd] : 0.f;
            float bs = fmaf(hq, ua, c0);
            gq2[dl] = f2b2(hq, hq);
            base2[dl] = f2b2(bs, bs);
            iv[dl] = (va && (l0 + dl) < LW) ? invA[dl*128 + qd] : 0.f;
        }
        int q4 = tid & 3;
        for (int jj = 0; jj < 17; jj++) {
            int b2 = 2*q4 + 8*jj;
            uint32_t gval2 = *(const uint32_t*)&Gm[a*GST + b2];
            uint32_t wb2 = ((const uint32_t*)Wvb)[b2 >> 1];
            float p0 = 0.f, p1 = 0.f;
#pragma unroll
            for (int dl = 0; dl < 8; dl++) {
                uint32_t hk2u = (dl & 1)
                    ? HP2O[(b2 - dl + 7) >> 1]
                    : HP2E[(b2 - dl + 8) >> 1];
                __nv_bfloat162 s2 = __hfma2(
                    __hfma2(u2b(gq2[dl]), u2b(gval2), u2b(wb2)),
                    u2b(hk2u), u2b(base2[dl]));
                float2 sf = __bfloat1622float2(s2);
                float2 hk = b2f(hk2u);
                p0 = fmaf(hk.x*iv[dl], exp2f(sf.x), p0);
                p1 = fmaf(hk.y*iv[dl], exp2f(sf.y), p1);
            }
            *(uint32_t*)&Gm[a*GST + b2] = f2b2(p0, p1);
        }
    }
    __syncthreads();

    // ---- PV (HFMA2 + f32 flush, LDS.128 V loads) ----
    for (int idx = tid; idx < 68*8; idx += ATHREADS) {
        int ta = idx >> 3, tj = idx & 7;
        int a0 = ta*2, j0 = tj*8;
        float2 accf[2][4];
#pragma unroll
        for (int i = 0; i < 2; i++)
#pragma unroll
            for (int c = 0; c < 4; c++) accf[i][c] = make_float2(0.f, 0.f);
        __nv_bfloat162 z2 = __float2bfloat162_rn(0.f);
        for (int cb = 0; cb < 68; cb += 8) {
            int ce = (cb + 8 < 68) ? cb + 8 : 68;
            __nv_bfloat162 acc2[2][4];
#pragma unroll
            for (int i = 0; i < 2; i++)
#pragma unroll
                for (int c = 0; c < 4; c++) acc2[i][c] = z2;
            for (int bw = cb; bw < ce; bw++) {
                uint4 V0 = *(const uint4*)&Zv[(2*bw)*ZST + (j0 >> 1)];
                uint4 V1 = *(const uint4*)&Zv[(2*bw+1)*ZST + (j0 >> 1)];
#pragma unroll
                for (int i = 0; i < 2; i++) {
                    __nv_bfloat162 pp = u2b(*(const uint32_t*)&Gm[(a0+i)*GST + 2*bw]);
                    __nv_bfloat162 pl = __low2bfloat162(pp);
                    __nv_bfloat162 ph = __high2bfloat162(pp);
                    acc2[i][0] = __hfma2(pl, u2b(V0.x), acc2[i][0]);
                    acc2[i][1] = __hfma2(pl, u2b(V0.y), acc2[i][1]);
                    acc2[i][2] = __hfma2(pl, u2b(V0.z), acc2[i][2]);
                    acc2[i][3] = __hfma2(pl, u2b(V0.w), acc2[i][3]);
                    acc2[i][0] = __hfma2(ph, u2b(V1.x), acc2[i][0]);
                    acc2[i][1] = __hfma2(ph, u2b(V1.y), acc2[i][1]);
                    acc2[i][2] = __hfma2(ph, u2b(V1.z), acc2[i][2]);
                    acc2[i][3] = __hfma2(ph, u2b(V1.w), acc2[i][3]);
                }
            }
#pragma unroll
            for (int i = 0; i < 2; i++)
#pragma unroll
                for (int c = 0; c < 4; c++) {
                    float2 f = __bfloat1622float2(acc2[i][c]);
                    accf[i][c].x += f.x;
                    accf[i][c].y += f.y;
                }
        }
#pragma unroll
        for (int i = 0; i < 2; i++) {
            int tp = l0 + a0 + i;
            if (tp < TPP) {
                float* dst = &g_acc[((size_t)v*TPP + tp)*CC + h*64 + j0];
#pragma unroll
                for (int c = 0; c < 4; c++) {
                    atomicAdd(&dst[2*c],   accf[i][c].x);
                    atomicAdd(&dst[2*c+1], accf[i][c].y);
                }
                if (dual) {
                    float* dst2 = &g_acc[((size_t)TPP + tp + SHIFTN)*CC + h*64 + j0];
#pragma unroll
                    for (int c = 0; c < 4; c++) {
                        atomicAdd(&dst2[2*c],   accf[i][c].x);
                        atomicAdd(&dst2[2*c+1], accf[i][c].y);
                    }
                }
            }
        }
    }
}

// ---------------- finalize (split-c, 512 thr) ----------------------------
__global__ __launch_bounds__(512) void k_finalize(const float* __restrict__ inb,
                                                  const float* __restrict__ ob,
                                                  const float* __restrict__ pb) {
    __shared__ float U[4][CC];
    __shared__ float Y2[4][CC];
    __shared__ float P[4][CC];
    __shared__ float bb[4];
    int tid = threadIdx.x, half = tid >> 8, col = tid & 255;
    int t0 = blockIdx.x * 4;

    for (int idx = tid; idx < 4*CC; idx += 512) {
        int r = idx >> 8, c = idx & 255;
        float bvv = inb[2*CC + c];
        int t = t0 + r;
        float cm = cntf(t);
        float am = g_acc[(size_t)(t + PADN)*CC + c];
        float pm = (am + cm*bvv) / (cm + 1e-6f);
        int tau = (t + SHIFTN) & (TT-1);
        float cs = cntf(tau);
        float as = g_acc[(size_t)TPP*CC + (size_t)(tau + PADN)*CC + c];
        float ps = (as + cs*bvv) / (cs + 1e-6f);
        U[r][c] = 0.5f*(pm + ps);
    }
    if (tid < 4) {
        int t = t0 + tid;
        float cm = cntf(t);
        float cs = cntf((t + SHIFTN) & (TT-1));
        bb[tid] = 0.5f*(cm/(cm + 1e-6f) + cs/(cs + 1e-6f));
    }
    __syncthreads();

    float acc[4];
    int cbase = half * 128;
#pragma unroll
    for (int r = 0; r < 4; r++) acc[r] = 0.f;
#pragma unroll 4
    for (int cc = 0; cc < 128; cc++) {
        int c = cbase + cc;
        float w = g_wto[c*CC + col];
#pragma unroll
        for (int r = 0; r < 4; r++) acc[r] += U[r][c]*w;
    }
    if (half) {
#pragma unroll
        for (int r = 0; r < 4; r++) P[r][col] = acc[r];
    }
    __syncthreads();
    if (!half) {
        float obv = ob[col];
#pragma unroll
        for (int r = 0; r < 4; r++)
            Y2[r][col] = acc[r] + P[r][col] + bb[r]*obv;
    }
    __syncthreads();

#pragma unroll
    for (int r = 0; r < 4; r++) acc[r] = 0.f;
#pragma unroll 4
    for (int cc = 0; cc < 128; cc++) {
        int c = cbase + cc;
        float w = g_wtp[c*CC + col];
#pragma unroll
        for (int r = 0; r < 4; r++) acc[r] += Y2[r][c]*w;
    }
    if (half) {
#pragma unroll
        for (int r = 0; r < 4; r++) P[r][col] = acc[r];
    }
    __syncthreads();
    if (!half) {
        float pbv = pb[col];
        float colpart = 0.f;
#pragma unroll
        for (int r = 0; r < 4; r++) {
            float yp = acc[r] + P[r][col] + pbv;
            g_y[(size_t)(t0 + r)*CC + col] = yp;
            colpart += yp;
        }
        atomicAdd(&g_colsum[col], colpart);
    }
}

// ---------------- SE gate ----------------
__global__ __launch_bounds__(256) void k_se(const float* __restrict__ w1,
                                            const float* __restrict__ w2) {
    __shared__ float s[CC], s1[16];
    int tid = threadIdx.x;
    s[tid] = g_colsum[tid] * (1.f/(float)TT);
    __syncthreads();
    if (tid < 16) {
        float a = 0.f;
        for (int c = 0; c < CC; c++) a += s[c]*w1[tid*CC + c];
        s1[tid] = fmaxf(a, 0.f);
    }
    __syncthreads();
    float a = 0.f;
#pragma unroll
    for (int j = 0; j < 16; j++) a += s1[j]*w2[tid*16 + j];
    g_segate[tid] = 1.f/(1.f + __expf(-a));
}

// ---------------- residual + gate ----------------
__global__ void k_out(const float* __restrict__ x, float* __restrict__ out) {
    int i = blockIdx.x*256 + threadIdx.x;
    out[i] = x[i] + g_y[i]*g_segate[i & 255];
}

extern "C" void kernel_launch(void* const* d_in, const int* in_sizes, int n_in,
                              void* d_out, int out_size) {
    const float* x  = (const float*)d_in[0];
    const float* lg = (const float*)d_in[1];
    const float* lb = (const float*)d_in[2];
    const float* wi = (const float*)d_in[3];
    const float* ib = (const float*)d_in[4];
    const float* wo = (const float*)d_in[5];
    const float* ob = (const float*)d_in[6];
    const float* wp = (const float*)d_in[7];
    const float* pb = (const float*)d_in[8];
    const float* w1 = (const float*)d_in[9];
    const float* w2 = (const float*)d_in[10];
    float* out = (float*)d_out;

    cudaFuncSetAttribute(k_attn, cudaFuncAttributeMaxDynamicSharedMemorySize,
                         SMEM_BYTES);

    k_init<<<2300, 256>>>(wi, wo, wp);
    k_ln_z<<<256, 512>>>(x, lg, lb);
    k_attn<<<dim3(153, 4), ATHREADS, SMEM_BYTES>>>(ib);
    k_finalize<<<256, 512>>>(ib, ob, pb);
    k_se<<<1, 256>>>(w1, w2);
    k_out<<<1024, 256>>>(x, out);
}